// round 8
// baseline (speedup 1.0000x reference)
#include <cuda_runtime.h>
#include <cstdint>

typedef unsigned long long ull;

#define T_STEPS 8
#define NN 20000
#define EE 320000
#define ET (EE + NN)

// ---------------- scratch (static device globals; no allocation at run time) ------------
__device__ __align__(16) float g_h1lin[NN * 256];
__device__ __align__(16) float g_als1[NN * 4];
__device__ __align__(16) float g_ald1[NN * 4];
__device__ __align__(16) float g_ex1[ET * 4];
__device__ __align__(16) float g_sum1[NN * 4];
__device__ __align__(16) float g_out1[NN * 256];
__device__ __align__(16) float g_h2lin[NN * 64];
__device__ __align__(16) float g_als2[NN];
__device__ __align__(16) float g_ald2[NN];
__device__ __align__(16) float g_ex2[ET];
__device__ __align__(16) float g_sum2[NN];
__device__ __align__(16) float g_h2[NN * 64];
__device__ __align__(16) float g_P[NN * 384];
__device__ __align__(16) float g_Q[NN * 384];
__device__ __align__(16) float g_gi[(size_t)EE * 384];
__device__ __align__(16) float g_gh[(size_t)EE * 384];
__device__ __align__(16) float g_h0[(size_t)EE * 128];
__device__ __align__(16) float g_h1s[(size_t)EE * 128];
__device__ __align__(16) float g_dec1[(size_t)EE * 64];

// ---------------- packed fp32x2 helpers (sm_103a FFMA2) ------------
__device__ __forceinline__ ull dup2(float x) {
    ull r;
    unsigned u = __float_as_uint(x);
    asm("mov.b64 %0, {%1, %1};" : "=l"(r) : "r"(u));
    return r;
}
__device__ __forceinline__ ull ffma2(ull a, ull b, ull c) {
    ull d;
    asm("fma.rn.f32x2 %0, %1, %2, %3;" : "=l"(d) : "l"(a), "l"(b), "l"(c));
    return d;
}

// ---------------- GEMM: C[M,Ntot] = A[M,K] * B (+bias) ------------
// B_NK = true : B is [Ntot, K] row-major with row stride ldb   (C = A * B^T)
// B_NK = false: B is [K, Ntot] row-major with row stride ldb   (C = A * B)
// Tile 128x64, BK=16, 256 threads, 8x4 per thread, FFMA2 pairs along M.
template <bool B_NK, bool RELU>
__global__ void __launch_bounds__(256) sgemm_kernel(
    const float* __restrict__ A, const float* __restrict__ B,
    const float* __restrict__ bias, float* __restrict__ C,
    int M, int K, int ldb, int ldc)
{
    __shared__ float As[16][128];
    __shared__ float Bs[16][64];
    const int tid = threadIdx.x;
    const int m0 = blockIdx.x * 128;
    const int n0 = blockIdx.y * 64;
    const int tx = tid & 15;   // n direction
    const int ty = tid >> 4;   // m direction

    ull acc[4][4];
#pragma unroll
    for (int i = 0; i < 4; i++)
#pragma unroll
        for (int j = 0; j < 4; j++) acc[i][j] = 0ULL;

    const int ar = tid >> 2;          // 0..63
    const int ac = (tid & 3) << 2;    // 0,4,8,12
    const int nIter = K >> 4;         // K % 16 == 0 by construction

    for (int it = 0; it < nIter; ++it) {
        const int k0 = it << 4;
        // load A tile (transposed into smem), guard M
#pragma unroll
        for (int half = 0; half < 2; ++half) {
            int row = ar + half * 64;
            float4 v = make_float4(0.f, 0.f, 0.f, 0.f);
            if (m0 + row < M)
                v = *reinterpret_cast<const float4*>(A + (size_t)(m0 + row) * K + k0 + ac);
            As[ac + 0][row] = v.x; As[ac + 1][row] = v.y;
            As[ac + 2][row] = v.z; As[ac + 3][row] = v.w;
        }
        // load B tile
        if (B_NK) {
            int n = tid >> 2;  // 0..63
            float4 v = *reinterpret_cast<const float4*>(B + (size_t)(n0 + n) * ldb + k0 + ac);
            Bs[ac + 0][n] = v.x; Bs[ac + 1][n] = v.y;
            Bs[ac + 2][n] = v.z; Bs[ac + 3][n] = v.w;
        } else {
            int kk = tid >> 4;          // 0..15
            int nn = (tid & 15) << 2;   // 0..60
            *reinterpret_cast<float4*>(&Bs[kk][nn]) =
                *reinterpret_cast<const float4*>(B + (size_t)(k0 + kk) * ldb + n0 + nn);
        }
        __syncthreads();
#pragma unroll
        for (int kk = 0; kk < 16; ++kk) {
            ulonglong2 aA = *reinterpret_cast<const ulonglong2*>(&As[kk][ty * 8]);
            ulonglong2 aB = *reinterpret_cast<const ulonglong2*>(&As[kk][ty * 8 + 4]);
            float4 b = *reinterpret_cast<const float4*>(&Bs[kk][tx * 4]);
            ull am0 = aA.x, am1 = aA.y, am2 = aB.x, am3 = aB.y;
            ull bb0 = dup2(b.x), bb1 = dup2(b.y), bb2 = dup2(b.z), bb3 = dup2(b.w);
            acc[0][0] = ffma2(am0, bb0, acc[0][0]); acc[0][1] = ffma2(am0, bb1, acc[0][1]);
            acc[0][2] = ffma2(am0, bb2, acc[0][2]); acc[0][3] = ffma2(am0, bb3, acc[0][3]);
            acc[1][0] = ffma2(am1, bb0, acc[1][0]); acc[1][1] = ffma2(am1, bb1, acc[1][1]);
            acc[1][2] = ffma2(am1, bb2, acc[1][2]); acc[1][3] = ffma2(am1, bb3, acc[1][3]);
            acc[2][0] = ffma2(am2, bb0, acc[2][0]); acc[2][1] = ffma2(am2, bb1, acc[2][1]);
            acc[2][2] = ffma2(am2, bb2, acc[2][2]); acc[2][3] = ffma2(am2, bb3, acc[2][3]);
            acc[3][0] = ffma2(am3, bb0, acc[3][0]); acc[3][1] = ffma2(am3, bb1, acc[3][1]);
            acc[3][2] = ffma2(am3, bb2, acc[3][2]); acc[3][3] = ffma2(am3, bb3, acc[3][3]);
        }
        __syncthreads();
    }

    float4 bv = make_float4(0.f, 0.f, 0.f, 0.f);
    if (bias) bv = *reinterpret_cast<const float4*>(bias + n0 + tx * 4);
#pragma unroll
    for (int i = 0; i < 4; i++) {
        float lo[4], hi[4];
#pragma unroll
        for (int j = 0; j < 4; j++) {
            lo[j] = __uint_as_float((unsigned)(acc[i][j] & 0xffffffffULL));
            hi[j] = __uint_as_float((unsigned)(acc[i][j] >> 32));
        }
        float4 ce = make_float4(lo[0] + bv.x, lo[1] + bv.y, lo[2] + bv.z, lo[3] + bv.w);
        float4 co = make_float4(hi[0] + bv.x, hi[1] + bv.y, hi[2] + bv.z, hi[3] + bv.w);
        if (RELU) {
            ce.x = fmaxf(ce.x, 0.f); ce.y = fmaxf(ce.y, 0.f);
            ce.z = fmaxf(ce.z, 0.f); ce.w = fmaxf(ce.w, 0.f);
            co.x = fmaxf(co.x, 0.f); co.y = fmaxf(co.y, 0.f);
            co.z = fmaxf(co.z, 0.f); co.w = fmaxf(co.w, 0.f);
        }
        int m = m0 + ty * 8 + i * 2;
        if (m < M)
            *reinterpret_cast<float4*>(C + (size_t)m * ldc + n0 + tx * 4) = ce;
        if (m + 1 < M)
            *reinterpret_cast<float4*>(C + (size_t)(m + 1) * ldc + n0 + tx * 4) = co;
    }
}

// ---------------- GAT attention logits ------------
__global__ void alpha4_kernel(const float* __restrict__ h, const float* __restrict__ av,
                              const float* __restrict__ dv, float* __restrict__ als,
                              float* __restrict__ ald)
{
    int idx = blockIdx.x * blockDim.x + threadIdx.x;
    if (idx >= NN * 4) return;
    int i = idx >> 2, hh = idx & 3;
    const float* hp = h + (size_t)i * 256 + hh * 64;
    const float* ap = av + hh * 64;
    const float* dp = dv + hh * 64;
    float ss = 0.f, sd = 0.f;
#pragma unroll
    for (int c = 0; c < 64; c++) { float v = hp[c]; ss += v * ap[c]; sd += v * dp[c]; }
    als[idx] = ss; ald[idx] = sd;
}

__global__ void alpha1_kernel(const float* __restrict__ h, const float* __restrict__ av,
                              const float* __restrict__ dv, float* __restrict__ als,
                              float* __restrict__ ald)
{
    int i = blockIdx.x * blockDim.x + threadIdx.x;
    if (i >= NN) return;
    const float* hp = h + (size_t)i * 64;
    float ss = 0.f, sd = 0.f;
#pragma unroll
    for (int c = 0; c < 64; c++) { float v = hp[c]; ss += v * av[c]; sd += v * dv[c]; }
    als[i] = ss; ald[i] = sd;
}

// ---------------- edge softmax numerator + denominator (max-shift skipped: exact softmax) --
template <int H>
__global__ void edge_exp_kernel(const int* __restrict__ ei, const float* __restrict__ als,
                                const float* __restrict__ ald, float* __restrict__ exbuf,
                                float* __restrict__ sums)
{
    int idx = blockIdx.x * blockDim.x + threadIdx.x;
    if (idx >= ET * H) return;
    int k = idx / H, hh = idx % H;
    int s, d;
    if (k < EE) { s = ei[k]; d = ei[EE + k]; } else { s = k - EE; d = s; }
    float e = als[s * H + hh] + ald[d * H + hh];
    e = (e >= 0.f) ? e : 0.2f * e;      // leaky_relu(0.2)
    float ex = expf(e);
    exbuf[(size_t)k * H + hh] = ex;
    atomicAdd(&sums[d * H + hh], ex);
}

// ---------------- weighted scatter aggregation ------------
template <int HC, int C>
__global__ void edge_agg_kernel(const int* __restrict__ ei, const float* __restrict__ hlin,
                                const float* __restrict__ exbuf, const float* __restrict__ sums,
                                float* __restrict__ outp)
{
    int idx = blockIdx.x * blockDim.x + threadIdx.x;
    if (idx >= ET * HC) return;
    int k = idx / HC, r = idx % HC;
    constexpr int H = HC / C;
    int hh = r / C;
    int s, d;
    if (k < EE) { s = ei[k]; d = ei[EE + k]; } else { s = k - EE; d = s; }
    float att = exbuf[(size_t)k * H + hh] / (sums[d * H + hh] + 1e-16f);
    atomicAdd(&outp[(size_t)d * HC + r], hlin[(size_t)s * HC + r] * att);
}

// ---------------- pointwise ------------
__global__ void elu_bias_kernel(float* __restrict__ x, const float* __restrict__ b, int total, int C)
{
    int i = blockIdx.x * blockDim.x + threadIdx.x;
    if (i >= total) return;
    float v = x[i] + b[i % C];
    x[i] = (v > 0.f) ? v : expm1f(v);
}
__global__ void bias_kernel(float* __restrict__ x, const float* __restrict__ b, int total, int C)
{
    int i = blockIdx.x * blockDim.x + threadIdx.x;
    if (i >= total) return;
    x[i] += b[i % C];
}

// ---------------- GRU gates ------------
// layer 0: gi gathered as P[src] + Q[dst] (node-level factorization of emb @ Wih0^T)
__global__ void gru_gate0_kernel(const int* __restrict__ ei, const float* __restrict__ P,
                                 const float* __restrict__ Q, const float* __restrict__ gh,
                                 float* __restrict__ h)
{
    int idx = blockIdx.x * blockDim.x + threadIdx.x;
    if (idx >= EE * 128) return;
    int e = idx >> 7, j = idx & 127;
    int s = ei[e], d = ei[EE + e];
    const float* Ps = P + (size_t)s * 384;
    const float* Qd = Q + (size_t)d * 384;
    const float* g = gh + (size_t)e * 384;
    float ir = Ps[j] + Qd[j];
    float iz = Ps[128 + j] + Qd[128 + j];
    float in_ = Ps[256 + j] + Qd[256 + j];
    float hr = g[j], hz = g[128 + j], hn = g[256 + j];
    float r = 1.f / (1.f + expf(-(ir + hr)));
    float z = 1.f / (1.f + expf(-(iz + hz)));
    float n = tanhf(in_ + r * hn);
    float hp = h[idx];
    h[idx] = (1.f - z) * n + z * hp;
}

__global__ void gru_gate_kernel(const float* __restrict__ gi, const float* __restrict__ gh,
                                float* __restrict__ h)
{
    int idx = blockIdx.x * blockDim.x + threadIdx.x;
    if (idx >= EE * 128) return;
    int e = idx >> 7, j = idx & 127;
    const float* gip = gi + (size_t)e * 384;
    const float* ghp = gh + (size_t)e * 384;
    float r = 1.f / (1.f + expf(-(gip[j] + ghp[j])));
    float z = 1.f / (1.f + expf(-(gip[128 + j] + ghp[128 + j])));
    float n = tanhf(gip[256 + j] + r * ghp[256 + j]);
    float hp = h[idx];
    h[idx] = (1.f - z) * n + z * hp;
}

// ---------------- decoder stage 2 (GEMV N=1) ------------
__global__ void decoder2_kernel(const float* __restrict__ d1, const float* __restrict__ Wd2,
                                const float* __restrict__ bd2, float* __restrict__ out)
{
    int e = blockIdx.x * blockDim.x + threadIdx.x;
    if (e >= EE) return;
    const float* r = d1 + (size_t)e * 64;
    float s = 0.f;
#pragma unroll
    for (int c = 0; c < 64; c++) s += r[c] * Wd2[c];
    out[e] = s + bd2[0];
}

// ---------------- host orchestration ------------
static inline dim3 ggrid(int M, int Ntot) { return dim3((M + 127) / 128, Ntot / 64); }
static inline int gb(int n) { return (n + 255) / 256; }

extern "C" void kernel_launch(void* const* d_in, const int* in_sizes, int n_in,
                              void* d_out, int out_size)
{
    (void)in_sizes; (void)n_in; (void)out_size;
    const float* x_seq  = (const float*)d_in[0];
    const int*   ei     = (const int*)d_in[1];
    const float* W1     = (const float*)d_in[2];
    const float* a_src1 = (const float*)d_in[3];
    const float* a_dst1 = (const float*)d_in[4];
    const float* b1     = (const float*)d_in[5];
    const float* W2     = (const float*)d_in[6];
    const float* a_src2 = (const float*)d_in[7];
    const float* a_dst2 = (const float*)d_in[8];
    const float* b2     = (const float*)d_in[9];
    const float* Wih0   = (const float*)d_in[10];
    const float* Whh0   = (const float*)d_in[11];
    const float* bih0   = (const float*)d_in[12];
    const float* bhh0   = (const float*)d_in[13];
    const float* Wih1   = (const float*)d_in[14];
    const float* Whh1   = (const float*)d_in[15];
    const float* bih1   = (const float*)d_in[16];
    const float* bhh1   = (const float*)d_in[17];
    const float* Wd1    = (const float*)d_in[18];
    const float* bd1    = (const float*)d_in[19];
    const float* Wd2    = (const float*)d_in[20];
    const float* bd2    = (const float*)d_in[21];
    float* out = (float*)d_out;

    float *p_h1lin, *p_als1, *p_ald1, *p_ex1, *p_sum1, *p_out1;
    float *p_h2lin, *p_als2, *p_ald2, *p_ex2, *p_sum2, *p_h2;
    float *p_P, *p_Q, *p_gi, *p_gh, *p_h0, *p_h1s, *p_dec1;
    cudaGetSymbolAddress((void**)&p_h1lin, g_h1lin);
    cudaGetSymbolAddress((void**)&p_als1, g_als1);
    cudaGetSymbolAddress((void**)&p_ald1, g_ald1);
    cudaGetSymbolAddress((void**)&p_ex1, g_ex1);
    cudaGetSymbolAddress((void**)&p_sum1, g_sum1);
    cudaGetSymbolAddress((void**)&p_out1, g_out1);
    cudaGetSymbolAddress((void**)&p_h2lin, g_h2lin);
    cudaGetSymbolAddress((void**)&p_als2, g_als2);
    cudaGetSymbolAddress((void**)&p_ald2, g_ald2);
    cudaGetSymbolAddress((void**)&p_ex2, g_ex2);
    cudaGetSymbolAddress((void**)&p_sum2, g_sum2);
    cudaGetSymbolAddress((void**)&p_h2, g_h2);
    cudaGetSymbolAddress((void**)&p_P, g_P);
    cudaGetSymbolAddress((void**)&p_Q, g_Q);
    cudaGetSymbolAddress((void**)&p_gi, g_gi);
    cudaGetSymbolAddress((void**)&p_gh, g_gh);
    cudaGetSymbolAddress((void**)&p_h0, g_h0);
    cudaGetSymbolAddress((void**)&p_h1s, g_h1s);
    cudaGetSymbolAddress((void**)&p_dec1, g_dec1);

    // reset recurrent state every call (graph replays must be identical)
    cudaMemsetAsync(p_h0, 0, (size_t)EE * 128 * sizeof(float), 0);
    cudaMemsetAsync(p_h1s, 0, (size_t)EE * 128 * sizeof(float), 0);

    for (int t = 0; t < T_STEPS; ++t) {
        const float* x_t = x_seq + (size_t)t * NN * 32;

        // ---- GAT layer 1 ----
        cudaMemsetAsync(p_out1, 0, (size_t)NN * 256 * sizeof(float), 0);
        cudaMemsetAsync(p_sum1, 0, (size_t)NN * 4 * sizeof(float), 0);
        sgemm_kernel<false, false><<<ggrid(NN, 256), 256>>>(x_t, W1, nullptr, p_h1lin,
                                                            NN, 32, 256, 256);
        alpha4_kernel<<<gb(NN * 4), 256>>>(p_h1lin, a_src1, a_dst1, p_als1, p_ald1);
        edge_exp_kernel<4><<<gb(ET * 4), 256>>>(ei, p_als1, p_ald1, p_ex1, p_sum1);
        edge_agg_kernel<256, 64><<<gb(ET * 256), 256>>>(ei, p_h1lin, p_ex1, p_sum1, p_out1);
        elu_bias_kernel<<<gb(NN * 256), 256>>>(p_out1, b1, NN * 256, 256);

        // ---- GAT layer 2 ----
        cudaMemsetAsync(p_h2, 0, (size_t)NN * 64 * sizeof(float), 0);
        cudaMemsetAsync(p_sum2, 0, (size_t)NN * sizeof(float), 0);
        sgemm_kernel<false, false><<<ggrid(NN, 64), 256>>>(p_out1, W2, nullptr, p_h2lin,
                                                           NN, 256, 64, 64);
        alpha1_kernel<<<gb(NN), 256>>>(p_h2lin, a_src2, a_dst2, p_als2, p_ald2);
        edge_exp_kernel<1><<<gb(ET), 256>>>(ei, p_als2, p_ald2, p_ex2, p_sum2);
        edge_agg_kernel<64, 64><<<gb(ET * 64), 256>>>(ei, p_h2lin, p_ex2, p_sum2, p_h2);
        bias_kernel<<<gb(NN * 64), 256>>>(p_h2, b2, NN * 64, 64);

        // ---- GRU layer 0 (gi factored through node-level P/Q) ----
        sgemm_kernel<true, false><<<ggrid(NN, 384), 256>>>(p_h2, Wih0, bih0, p_P,
                                                           NN, 64, 128, 384);
        sgemm_kernel<true, false><<<ggrid(NN, 384), 256>>>(p_h2, Wih0 + 64, nullptr, p_Q,
                                                           NN, 64, 128, 384);
        sgemm_kernel<true, false><<<ggrid(EE, 384), 256>>>(p_h0, Whh0, bhh0, p_gh,
                                                           EE, 128, 128, 384);
        gru_gate0_kernel<<<gb(EE * 128), 256>>>(ei, p_P, p_Q, p_gh, p_h0);

        // ---- GRU layer 1 ----
        sgemm_kernel<true, false><<<ggrid(EE, 384), 256>>>(p_h0, Wih1, bih1, p_gi,
                                                           EE, 128, 128, 384);
        sgemm_kernel<true, false><<<ggrid(EE, 384), 256>>>(p_h1s, Whh1, bhh1, p_gh,
                                                           EE, 128, 128, 384);
        gru_gate_kernel<<<gb(EE * 128), 256>>>(p_gi, p_gh, p_h1s);
    }

    // ---- decoder ----
    sgemm_kernel<false, true><<<ggrid(EE, 64), 256>>>(p_h1s, Wd1, bd1, p_dec1,
                                                      EE, 128, 64, 64);
    decoder2_kernel<<<gb(EE), 256>>>(p_dec1, Wd2, bd2, out);
}

// round 11
// speedup vs baseline: 1.5123x; 1.5123x over previous
#include <cuda_runtime.h>
#include <cuda_bf16.h>
#include <cstdint>

typedef unsigned long long ull;

#define T_STEPS 8
#define NN 20000
#define EE 320000
#define ET (EE + NN)

// ---------------- scratch (static device globals; no allocation at run time) ------------
__device__ __align__(16) float g_h1lin[NN * 256];
__device__ __align__(16) float g_als1[NN * 4];
__device__ __align__(16) float g_ald1[NN * 4];
__device__ __align__(16) float g_ex1[ET * 4];
__device__ __align__(16) float g_sum1[NN * 4];
__device__ __align__(16) float g_out1[NN * 256];
__device__ __align__(16) float g_h2lin[NN * 64];
__device__ __align__(16) float g_als2[NN];
__device__ __align__(16) float g_ald2[NN];
__device__ __align__(16) float g_ex2[ET];
__device__ __align__(16) float g_sum2[NN];
__device__ __align__(16) float g_h2[NN * 64];
__device__ __align__(16) float g_P[NN * 384];
__device__ __align__(16) float g_Q[NN * 384];
__device__ __align__(16) float g_gi[(size_t)EE * 384];
__device__ __align__(16) float g_gh[(size_t)EE * 384];
__device__ __align__(16) float g_h0[(size_t)EE * 128];
__device__ __align__(16) float g_h1s[(size_t)EE * 128];
__device__ __align__(16) float g_dec1[(size_t)EE * 64];

// bf16 weight images [384][128] row-major:
// [0]=Whh0 hi, [1]=Whh0 lo, [2]=Wih1 hi, [3]=Wih1 lo, [4]=Whh1 hi, [5]=Whh1 lo
#define W_ELEMS (384 * 128)
__device__ __align__(16) __nv_bfloat16 g_wimg[6][W_ELEMS];

// ---------------- packed fp32x2 helpers (sm_103a FFMA2) ------------
__device__ __forceinline__ ull dup2(float x) {
    ull r;
    unsigned u = __float_as_uint(x);
    asm("mov.b64 %0, {%1, %1};" : "=l"(r) : "r"(u));
    return r;
}
__device__ __forceinline__ ull ffma2(ull a, ull b, ull c) {
    ull d;
    asm("fma.rn.f32x2 %0, %1, %2, %3;" : "=l"(d) : "l"(a), "l"(b), "l"(c));
    return d;
}

__device__ __forceinline__ uint32_t smem_u32(const void* p) {
    uint32_t a;
    asm("{ .reg .u64 t; cvta.to.shared.u64 t, %1; cvt.u32.u64 %0, t; }" : "=r"(a) : "l"(p));
    return a;
}

// ---------------- mma.sync helpers (family-portable: sm_80+) ------------
__device__ __forceinline__ void ldsm4(uint32_t* r, uint32_t addr) {
    asm volatile("ldmatrix.sync.aligned.m8n8.x4.shared.b16 {%0,%1,%2,%3}, [%4];"
        : "=r"(r[0]), "=r"(r[1]), "=r"(r[2]), "=r"(r[3]) : "r"(addr));
}
__device__ __forceinline__ void mma_bf16(float* c, const uint32_t* a, uint32_t b0, uint32_t b1) {
    asm volatile("mma.sync.aligned.m16n8k16.row.col.f32.bf16.bf16.f32 "
        "{%0,%1,%2,%3}, {%4,%5,%6,%7}, {%8,%9}, {%0,%1,%2,%3};"
        : "+f"(c[0]), "+f"(c[1]), "+f"(c[2]), "+f"(c[3])
        : "r"(a[0]), "r"(a[1]), "r"(a[2]), "r"(a[3]), "r"(b0), "r"(b1));
}

// SMEM layout for gemm_mma: padded rows, stride 136 bf16 (272 B) -> conflict-free ldmatrix
#define AHI_OFF 0
#define ALO_OFF 17408
#define BHI_OFF 34816
#define BLO_OFF 69632
#define SMEM_MMA 104448

// -------- one-time weight conversion: fp32 [384,128] -> bf16 hi/lo images --------
__global__ void conv_w_kernel(const float* __restrict__ W, __nv_bfloat16* __restrict__ hi,
                              __nv_bfloat16* __restrict__ lo)
{
    int idx = blockIdx.x * blockDim.x + threadIdx.x;
    if (idx >= W_ELEMS) return;
    float v = W[idx];
    __nv_bfloat16 h = __float2bfloat16_rn(v);
    hi[idx] = h;
    lo[idx] = __float2bfloat16_rn(v - __bfloat162float(h));
}

// -------- tensor GEMM: C[EE,384] = A[EE,128] @ W^T + bias, bf16 3-pass split --------
// grid (EE/64, 3); block 256 (8 warps, 2x4); warp tile 32x32; CTA tile 64x128.
__global__ void __launch_bounds__(256)
gemm_mma_kernel(const float* __restrict__ A, const uint4* __restrict__ Bhi,
                const uint4* __restrict__ Blo, const float* __restrict__ bias,
                float* __restrict__ C)
{
    extern __shared__ char sm[];
    const int tid = threadIdx.x;
    const int lane = tid & 31, warp = tid >> 5;
    const int m0 = blockIdx.x * 64;
    const int n0g = blockIdx.y * 128;

    // ---- copy B chunk (hi+lo), inserting row padding (128 bf16 -> stride 136) ----
    {
        const uint4* sh = Bhi + (size_t)blockIdx.y * 2048;   // 128 rows * 16 uint4
        const uint4* sl = Blo + (size_t)blockIdx.y * 2048;
#pragma unroll
        for (int rep = 0; rep < 8; rep++) {
            int i = rep * 256 + tid;
            int n = i >> 4, seg = i & 15;
            int doff = n * 272 + seg * 16;
            *(uint4*)(sm + BHI_OFF + doff) = sh[i];
            *(uint4*)(sm + BLO_OFF + doff) = sl[i];
        }
    }

    // ---- load A tile [64 x 128] fp32, split to bf16 hi/lo into padded SMEM ----
    {
        const float4* Ap = (const float4*)(A + (size_t)m0 * 128);
#pragma unroll
        for (int rep = 0; rep < 8; rep++) {
            int flat = rep * 256 + tid;            // float4 index, 2048 total
            float4 v = Ap[flat];
            int m = flat >> 5, k = (flat & 31) << 2;
            __nv_bfloat162 h01 = __float22bfloat162_rn(make_float2(v.x, v.y));
            __nv_bfloat162 h23 = __float22bfloat162_rn(make_float2(v.z, v.w));
            float2 f01 = __bfloat1622float2(h01);
            float2 f23 = __bfloat1622float2(h23);
            __nv_bfloat162 l01 = __float22bfloat162_rn(make_float2(v.x - f01.x, v.y - f01.y));
            __nv_bfloat162 l23 = __float22bfloat162_rn(make_float2(v.z - f23.x, v.w - f23.y));
            int doff = m * 272 + k * 2;
            *(uint2*)(sm + AHI_OFF + doff) = make_uint2(*(unsigned*)&h01, *(unsigned*)&h23);
            *(uint2*)(sm + ALO_OFF + doff) = make_uint2(*(unsigned*)&l01, *(unsigned*)&l23);
        }
    }
    __syncthreads();

    // ---- MMA mainphase: all operands SMEM-resident, K=128 (8 ksteps), 3 passes ----
    const int wm = (warp >> 2) * 32;   // warp rows: 2 x 32
    const int wn = (warp & 3) * 32;    // warp cols: 4 x 32
    const uint32_t sb = smem_u32(sm);
    // A frag addrs: lanes 0-15 -> rows 0-15 @ k0; lanes 16-31 -> rows 0-15 @ k0+8
    const uint32_t a_base = sb + AHI_OFF +
        (uint32_t)((wm + (lane & 15)) * 272 + ((lane >> 4) << 4));
    // B frag addrs: lanes 0-7 n0..7@k0 | 8-15 n0..7@k0+8 | 16-23 n8..15@k0 | 24-31 n8..15@k0+8
    const uint32_t b_base = sb + BHI_OFF +
        (uint32_t)((wn + (lane & 7) + ((lane >> 4) << 3)) * 272 + (((lane >> 3) & 1) << 4));

    float acc[2][4][4];
#pragma unroll
    for (int i = 0; i < 2; i++)
#pragma unroll
        for (int j = 0; j < 4; j++)
#pragma unroll
            for (int q = 0; q < 4; q++) acc[i][j][q] = 0.f;

#pragma unroll 1
    for (int pass = 0; pass < 3; pass++) {
        const uint32_t aa = a_base + ((pass == 1) ? (ALO_OFF - AHI_OFF) : 0u);
        const uint32_t bb = b_base + ((pass == 2) ? (BLO_OFF - BHI_OFF) : 0u);
#pragma unroll
        for (int ks = 0; ks < 8; ks++) {
            uint32_t af[2][4], bf[2][4];
            ldsm4(af[0], aa + ks * 32);
            ldsm4(af[1], aa + 4352 + ks * 32);      // +16 rows
            ldsm4(bf[0], bb + ks * 32);
            ldsm4(bf[1], bb + 4352 + ks * 32);      // +16 n
#pragma unroll
            for (int mf = 0; mf < 2; mf++)
#pragma unroll
                for (int nf = 0; nf < 4; nf++)
                    mma_bf16(acc[mf][nf], af[mf],
                             bf[nf >> 1][(nf & 1) * 2], bf[nf >> 1][(nf & 1) * 2 + 1]);
        }
    }

    // ---- epilogue: add bias, store fp32 ----
    const int g = lane >> 2, t = lane & 3;
#pragma unroll
    for (int nf = 0; nf < 4; nf++) {
        int col = n0g + wn + nf * 8 + t * 2;
        float2 bv = *(const float2*)(bias + col);
#pragma unroll
        for (int mf = 0; mf < 2; mf++) {
            int row = m0 + wm + mf * 16 + g;
            float* cp = C + (size_t)row * 384 + col;
            *(float2*)cp = make_float2(acc[mf][nf][0] + bv.x, acc[mf][nf][1] + bv.y);
            *(float2*)(cp + 8 * 384) = make_float2(acc[mf][nf][2] + bv.x, acc[mf][nf][3] + bv.y);
        }
    }
}

// ---------------- scalar FFMA2 GEMM (small GEMMs): C = A * B (+bias) ------------
template <bool B_NK, bool RELU>
__global__ void __launch_bounds__(256) sgemm_kernel(
    const float* __restrict__ A, const float* __restrict__ B,
    const float* __restrict__ bias, float* __restrict__ C,
    int M, int K, int ldb, int ldc)
{
    __shared__ float As[16][128];
    __shared__ float Bs[16][64];
    const int tid = threadIdx.x;
    const int m0 = blockIdx.x * 128;
    const int n0 = blockIdx.y * 64;
    const int tx = tid & 15;
    const int ty = tid >> 4;

    ull acc[4][4];
#pragma unroll
    for (int i = 0; i < 4; i++)
#pragma unroll
        for (int j = 0; j < 4; j++) acc[i][j] = 0ULL;

    const int ar = tid >> 2;
    const int ac = (tid & 3) << 2;
    const int nIter = K >> 4;

    for (int it = 0; it < nIter; ++it) {
        const int k0 = it << 4;
#pragma unroll
        for (int half = 0; half < 2; ++half) {
            int row = ar + half * 64;
            float4 v = make_float4(0.f, 0.f, 0.f, 0.f);
            if (m0 + row < M)
                v = *reinterpret_cast<const float4*>(A + (size_t)(m0 + row) * K + k0 + ac);
            As[ac + 0][row] = v.x; As[ac + 1][row] = v.y;
            As[ac + 2][row] = v.z; As[ac + 3][row] = v.w;
        }
        if (B_NK) {
            int n = tid >> 2;
            float4 v = *reinterpret_cast<const float4*>(B + (size_t)(n0 + n) * ldb + k0 + ac);
            Bs[ac + 0][n] = v.x; Bs[ac + 1][n] = v.y;
            Bs[ac + 2][n] = v.z; Bs[ac + 3][n] = v.w;
        } else {
            int kk = tid >> 4;
            int nn = (tid & 15) << 2;
            *reinterpret_cast<float4*>(&Bs[kk][nn]) =
                *reinterpret_cast<const float4*>(B + (size_t)(k0 + kk) * ldb + n0 + nn);
        }
        __syncthreads();
#pragma unroll
        for (int kk = 0; kk < 16; ++kk) {
            ulonglong2 aA = *reinterpret_cast<const ulonglong2*>(&As[kk][ty * 8]);
            ulonglong2 aB = *reinterpret_cast<const ulonglong2*>(&As[kk][ty * 8 + 4]);
            float4 b = *reinterpret_cast<const float4*>(&Bs[kk][tx * 4]);
            ull am0 = aA.x, am1 = aA.y, am2 = aB.x, am3 = aB.y;
            ull bb0 = dup2(b.x), bb1 = dup2(b.y), bb2 = dup2(b.z), bb3 = dup2(b.w);
            acc[0][0] = ffma2(am0, bb0, acc[0][0]); acc[0][1] = ffma2(am0, bb1, acc[0][1]);
            acc[0][2] = ffma2(am0, bb2, acc[0][2]); acc[0][3] = ffma2(am0, bb3, acc[0][3]);
            acc[1][0] = ffma2(am1, bb0, acc[1][0]); acc[1][1] = ffma2(am1, bb1, acc[1][1]);
            acc[1][2] = ffma2(am1, bb2, acc[1][2]); acc[1][3] = ffma2(am1, bb3, acc[1][3]);
            acc[2][0] = ffma2(am2, bb0, acc[2][0]); acc[2][1] = ffma2(am2, bb1, acc[2][1]);
            acc[2][2] = ffma2(am2, bb2, acc[2][2]); acc[2][3] = ffma2(am2, bb3, acc[2][3]);
            acc[3][0] = ffma2(am3, bb0, acc[3][0]); acc[3][1] = ffma2(am3, bb1, acc[3][1]);
            acc[3][2] = ffma2(am3, bb2, acc[3][2]); acc[3][3] = ffma2(am3, bb3, acc[3][3]);
        }
        __syncthreads();
    }

    float4 bv = make_float4(0.f, 0.f, 0.f, 0.f);
    if (bias) bv = *reinterpret_cast<const float4*>(bias + n0 + tx * 4);
#pragma unroll
    for (int i = 0; i < 4; i++) {
        float lo[4], hi[4];
#pragma unroll
        for (int j = 0; j < 4; j++) {
            lo[j] = __uint_as_float((unsigned)(acc[i][j] & 0xffffffffULL));
            hi[j] = __uint_as_float((unsigned)(acc[i][j] >> 32));
        }
        float4 ce = make_float4(lo[0] + bv.x, lo[1] + bv.y, lo[2] + bv.z, lo[3] + bv.w);
        float4 co = make_float4(hi[0] + bv.x, hi[1] + bv.y, hi[2] + bv.z, hi[3] + bv.w);
        if (RELU) {
            ce.x = fmaxf(ce.x, 0.f); ce.y = fmaxf(ce.y, 0.f);
            ce.z = fmaxf(ce.z, 0.f); ce.w = fmaxf(ce.w, 0.f);
            co.x = fmaxf(co.x, 0.f); co.y = fmaxf(co.y, 0.f);
            co.z = fmaxf(co.z, 0.f); co.w = fmaxf(co.w, 0.f);
        }
        int m = m0 + ty * 8 + i * 2;
        if (m < M)
            *reinterpret_cast<float4*>(C + (size_t)m * ldc + n0 + tx * 4) = ce;
        if (m + 1 < M)
            *reinterpret_cast<float4*>(C + (size_t)(m + 1) * ldc + n0 + tx * 4) = co;
    }
}

// ---------------- GAT attention logits ------------
__global__ void alpha4_kernel(const float* __restrict__ h, const float* __restrict__ av,
                              const float* __restrict__ dv, float* __restrict__ als,
                              float* __restrict__ ald)
{
    int idx = blockIdx.x * blockDim.x + threadIdx.x;
    if (idx >= NN * 4) return;
    int i = idx >> 2, hh = idx & 3;
    const float* hp = h + (size_t)i * 256 + hh * 64;
    const float* ap = av + hh * 64;
    const float* dp = dv + hh * 64;
    float ss = 0.f, sd = 0.f;
#pragma unroll
    for (int c = 0; c < 64; c++) { float v = hp[c]; ss += v * ap[c]; sd += v * dp[c]; }
    als[idx] = ss; ald[idx] = sd;
}

__global__ void alpha1_kernel(const float* __restrict__ h, const float* __restrict__ av,
                              const float* __restrict__ dv, float* __restrict__ als,
                              float* __restrict__ ald)
{
    int i = blockIdx.x * blockDim.x + threadIdx.x;
    if (i >= NN) return;
    const float* hp = h + (size_t)i * 64;
    float ss = 0.f, sd = 0.f;
#pragma unroll
    for (int c = 0; c < 64; c++) { float v = hp[c]; ss += v * av[c]; sd += v * dv[c]; }
    als[i] = ss; ald[i] = sd;
}

// ---------------- edge softmax numerator + denominator ------------
template <int H>
__global__ void edge_exp_kernel(const int* __restrict__ ei, const float* __restrict__ als,
                                const float* __restrict__ ald, float* __restrict__ exbuf,
                                float* __restrict__ sums)
{
    int idx = blockIdx.x * blockDim.x + threadIdx.x;
    if (idx >= ET * H) return;
    int k = idx / H, hh = idx % H;
    int s, d;
    if (k < EE) { s = ei[k]; d = ei[EE + k]; } else { s = k - EE; d = s; }
    float e = als[s * H + hh] + ald[d * H + hh];
    e = (e >= 0.f) ? e : 0.2f * e;
    float ex = expf(e);
    exbuf[(size_t)k * H + hh] = ex;
    atomicAdd(&sums[d * H + hh], ex);
}

// ---------------- weighted scatter aggregation ------------
template <int HC, int C>
__global__ void edge_agg_kernel(const int* __restrict__ ei, const float* __restrict__ hlin,
                                const float* __restrict__ exbuf, const float* __restrict__ sums,
                                float* __restrict__ outp)
{
    int idx = blockIdx.x * blockDim.x + threadIdx.x;
    if (idx >= ET * HC) return;
    int k = idx / HC, r = idx % HC;
    constexpr int H = HC / C;
    int hh = r / C;
    int s, d;
    if (k < EE) { s = ei[k]; d = ei[EE + k]; } else { s = k - EE; d = s; }
    float att = exbuf[(size_t)k * H + hh] / (sums[d * H + hh] + 1e-16f);
    atomicAdd(&outp[(size_t)d * HC + r], hlin[(size_t)s * HC + r] * att);
}

// ---------------- pointwise ------------
__global__ void elu_bias_kernel(float* __restrict__ x, const float* __restrict__ b, int total, int C)
{
    int i = blockIdx.x * blockDim.x + threadIdx.x;
    if (i >= total) return;
    float v = x[i] + b[i % C];
    x[i] = (v > 0.f) ? v : expm1f(v);
}
__global__ void bias_kernel(float* __restrict__ x, const float* __restrict__ b, int total, int C)
{
    int i = blockIdx.x * blockDim.x + threadIdx.x;
    if (i >= total) return;
    x[i] += b[i % C];
}

// ---------------- GRU gates ------------
__global__ void gru_gate0_kernel(const int* __restrict__ ei, const float* __restrict__ P,
                                 const float* __restrict__ Q, const float* __restrict__ gh,
                                 float* __restrict__ h)
{
    int idx = blockIdx.x * blockDim.x + threadIdx.x;
    if (idx >= EE * 128) return;
    int e = idx >> 7, j = idx & 127;
    int s = ei[e], d = ei[EE + e];
    const float* Ps = P + (size_t)s * 384;
    const float* Qd = Q + (size_t)d * 384;
    const float* g = gh + (size_t)e * 384;
    float ir = Ps[j] + Qd[j];
    float iz = Ps[128 + j] + Qd[128 + j];
    float in_ = Ps[256 + j] + Qd[256 + j];
    float hr = g[j], hz = g[128 + j], hn = g[256 + j];
    float r = 1.f / (1.f + expf(-(ir + hr)));
    float z = 1.f / (1.f + expf(-(iz + hz)));
    float n = tanhf(in_ + r * hn);
    float hp = h[idx];
    h[idx] = (1.f - z) * n + z * hp;
}

__global__ void gru_gate_kernel(const float* __restrict__ gi, const float* __restrict__ gh,
                                float* __restrict__ h)
{
    int idx = blockIdx.x * blockDim.x + threadIdx.x;
    if (idx >= EE * 128) return;
    int e = idx >> 7, j = idx & 127;
    const float* gip = gi + (size_t)e * 384;
    const float* ghp = gh + (size_t)e * 384;
    float r = 1.f / (1.f + expf(-(gip[j] + ghp[j])));
    float z = 1.f / (1.f + expf(-(gip[128 + j] + ghp[128 + j])));
    float n = tanhf(gip[256 + j] + r * ghp[256 + j]);
    float hp = h[idx];
    h[idx] = (1.f - z) * n + z * hp;
}

// ---------------- decoder stage 2 ------------
__global__ void decoder2_kernel(const float* __restrict__ d1, const float* __restrict__ Wd2,
                                const float* __restrict__ bd2, float* __restrict__ out)
{
    int e = blockIdx.x * blockDim.x + threadIdx.x;
    if (e >= EE) return;
    const float* r = d1 + (size_t)e * 64;
    float s = 0.f;
#pragma unroll
    for (int c = 0; c < 64; c++) s += r[c] * Wd2[c];
    out[e] = s + bd2[0];
}

// ---------------- host orchestration ------------
static inline dim3 ggrid(int M, int Ntot) { return dim3((M + 127) / 128, Ntot / 64); }
static inline int gb(int n) { return (n + 255) / 256; }

extern "C" void kernel_launch(void* const* d_in, const int* in_sizes, int n_in,
                              void* d_out, int out_size)
{
    (void)in_sizes; (void)n_in; (void)out_size;
    const float* x_seq  = (const float*)d_in[0];
    const int*   ei     = (const int*)d_in[1];
    const float* W1     = (const float*)d_in[2];
    const float* a_src1 = (const float*)d_in[3];
    const float* a_dst1 = (const float*)d_in[4];
    const float* b1     = (const float*)d_in[5];
    const float* W2     = (const float*)d_in[6];
    const float* a_src2 = (const float*)d_in[7];
    const float* a_dst2 = (const float*)d_in[8];
    const float* b2     = (const float*)d_in[9];
    const float* Wih0   = (const float*)d_in[10];
    const float* Whh0   = (const float*)d_in[11];
    const float* bih0   = (const float*)d_in[12];
    const float* bhh0   = (const float*)d_in[13];
    const float* Wih1   = (const float*)d_in[14];
    const float* Whh1   = (const float*)d_in[15];
    const float* bih1   = (const float*)d_in[16];
    const float* bhh1   = (const float*)d_in[17];
    const float* Wd1    = (const float*)d_in[18];
    const float* bd1    = (const float*)d_in[19];
    const float* Wd2    = (const float*)d_in[20];
    const float* bd2    = (const float*)d_in[21];
    float* out = (float*)d_out;

    float *p_h1lin, *p_als1, *p_ald1, *p_ex1, *p_sum1, *p_out1;
    float *p_h2lin, *p_als2, *p_ald2, *p_ex2, *p_sum2, *p_h2;
    float *p_P, *p_Q, *p_gi, *p_gh, *p_h0, *p_h1s, *p_dec1;
    __nv_bfloat16* p_wimg;
    cudaGetSymbolAddress((void**)&p_h1lin, g_h1lin);
    cudaGetSymbolAddress((void**)&p_als1, g_als1);
    cudaGetSymbolAddress((void**)&p_ald1, g_ald1);
    cudaGetSymbolAddress((void**)&p_ex1, g_ex1);
    cudaGetSymbolAddress((void**)&p_sum1, g_sum1);
    cudaGetSymbolAddress((void**)&p_out1, g_out1);
    cudaGetSymbolAddress((void**)&p_h2lin, g_h2lin);
    cudaGetSymbolAddress((void**)&p_als2, g_als2);
    cudaGetSymbolAddress((void**)&p_ald2, g_ald2);
    cudaGetSymbolAddress((void**)&p_ex2, g_ex2);
    cudaGetSymbolAddress((void**)&p_sum2, g_sum2);
    cudaGetSymbolAddress((void**)&p_h2, g_h2);
    cudaGetSymbolAddress((void**)&p_P, g_P);
    cudaGetSymbolAddress((void**)&p_Q, g_Q);
    cudaGetSymbolAddress((void**)&p_gi, g_gi);
    cudaGetSymbolAddress((void**)&p_gh, g_gh);
    cudaGetSymbolAddress((void**)&p_h0, g_h0);
    cudaGetSymbolAddress((void**)&p_h1s, g_h1s);
    cudaGetSymbolAddress((void**)&p_dec1, g_dec1);
    cudaGetSymbolAddress((void**)&p_wimg, g_wimg);

    cudaFuncSetAttribute(gemm_mma_kernel, cudaFuncAttributeMaxDynamicSharedMemorySize, SMEM_MMA);

    const __nv_bfloat16* whh0h = p_wimg + 0 * W_ELEMS;
    const __nv_bfloat16* whh0l = p_wimg + 1 * W_ELEMS;
    const __nv_bfloat16* wih1h = p_wimg + 2 * W_ELEMS;
    const __nv_bfloat16* wih1l = p_wimg + 3 * W_ELEMS;
    const __nv_bfloat16* whh1h = p_wimg + 4 * W_ELEMS;
    const __nv_bfloat16* whh1l = p_wimg + 5 * W_ELEMS;

    // reset recurrent state every call
    cudaMemsetAsync(p_h0, 0, (size_t)EE * 128 * sizeof(float), 0);
    cudaMemsetAsync(p_h1s, 0, (size_t)EE * 128 * sizeof(float), 0);

    // weight conversion to bf16 hi/lo images
    conv_w_kernel<<<gb(W_ELEMS), 256>>>(Whh0, (__nv_bfloat16*)whh0h, (__nv_bfloat16*)whh0l);
    conv_w_kernel<<<gb(W_ELEMS), 256>>>(Wih1, (__nv_bfloat16*)wih1h, (__nv_bfloat16*)wih1l);
    conv_w_kernel<<<gb(W_ELEMS), 256>>>(Whh1, (__nv_bfloat16*)whh1h, (__nv_bfloat16*)whh1l);

    const dim3 mma_grid(EE / 64, 3);

    for (int t = 0; t < T_STEPS; ++t) {
        const float* x_t = x_seq + (size_t)t * NN * 32;

        // ---- GAT layer 1 ----
        cudaMemsetAsync(p_out1, 0, (size_t)NN * 256 * sizeof(float), 0);
        cudaMemsetAsync(p_sum1, 0, (size_t)NN * 4 * sizeof(float), 0);
        sgemm_kernel<false, false><<<ggrid(NN, 256), 256>>>(x_t, W1, nullptr, p_h1lin,
                                                            NN, 32, 256, 256);
        alpha4_kernel<<<gb(NN * 4), 256>>>(p_h1lin, a_src1, a_dst1, p_als1, p_ald1);
        edge_exp_kernel<4><<<gb(ET * 4), 256>>>(ei, p_als1, p_ald1, p_ex1, p_sum1);
        edge_agg_kernel<256, 64><<<gb(ET * 256), 256>>>(ei, p_h1lin, p_ex1, p_sum1, p_out1);
        elu_bias_kernel<<<gb(NN * 256), 256>>>(p_out1, b1, NN * 256, 256);

        // ---- GAT layer 2 ----
        cudaMemsetAsync(p_h2, 0, (size_t)NN * 64 * sizeof(float), 0);
        cudaMemsetAsync(p_sum2, 0, (size_t)NN * sizeof(float), 0);
        sgemm_kernel<false, false><<<ggrid(NN, 64), 256>>>(p_out1, W2, nullptr, p_h2lin,
                                                           NN, 256, 64, 64);
        alpha1_kernel<<<gb(NN), 256>>>(p_h2lin, a_src2, a_dst2, p_als2, p_ald2);
        edge_exp_kernel<1><<<gb(ET), 256>>>(ei, p_als2, p_ald2, p_ex2, p_sum2);
        edge_agg_kernel<64, 64><<<gb(ET * 64), 256>>>(ei, p_h2lin, p_ex2, p_sum2, p_h2);
        bias_kernel<<<gb(NN * 64), 256>>>(p_h2, b2, NN * 64, 64);

        // ---- GRU layer 0 (gi factored through node-level P/Q; gh via mma.sync) ----
        sgemm_kernel<true, false><<<ggrid(NN, 384), 256>>>(p_h2, Wih0, bih0, p_P,
                                                           NN, 64, 128, 384);
        sgemm_kernel<true, false><<<ggrid(NN, 384), 256>>>(p_h2, Wih0 + 64, nullptr, p_Q,
                                                           NN, 64, 128, 384);
        gemm_mma_kernel<<<mma_grid, 256, SMEM_MMA>>>(
            p_h0, (const uint4*)whh0h, (const uint4*)whh0l, bhh0, p_gh);
        gru_gate0_kernel<<<gb(EE * 128), 256>>>(ei, p_P, p_Q, p_gh, p_h0);

        // ---- GRU layer 1 (mma.sync) ----
        gemm_mma_kernel<<<mma_grid, 256, SMEM_MMA>>>(
            p_h0, (const uint4*)wih1h, (const uint4*)wih1l, bih1, p_gi);
        gemm_mma_kernel<<<mma_grid, 256, SMEM_MMA>>>(
            p_h1s, (const uint4*)whh1h, (const uint4*)whh1l, bhh1, p_gh);
        gru_gate_kernel<<<gb(EE * 128), 256>>>(p_gi, p_gh, p_h1s);
    }

    // ---- decoder ----
    sgemm_kernel<false, true><<<ggrid(EE, 64), 256>>>(p_h1s, Wd1, bd1, p_dec1,
                                                      EE, 128, 64, 64);
    decoder2_kernel<<<gb(EE), 256>>>(p_dec1, Wd2, bd2, out);
}

// round 13
// speedup vs baseline: 1.7839x; 1.1796x over previous
#include <cuda_runtime.h>
#include <cuda_bf16.h>
#include <cstdint>

typedef unsigned long long ull;

#define T_STEPS 8
#define NN 20000
#define EE 320000
#define ET (EE + NN)

// ---------------- scratch (static device globals; no allocation at run time) ------------
__device__ __align__(16) float g_h1lin[NN * 256];
__device__ __align__(16) float g_als1[NN * 4];
__device__ __align__(16) float g_ald1[NN * 4];
__device__ __align__(16) float g_ex1[ET * 4];
__device__ __align__(16) float g_sum1[NN * 4];
__device__ __align__(16) float g_out1[NN * 256];
__device__ __align__(16) float g_h2lin[NN * 64];
__device__ __align__(16) float g_als2[NN];
__device__ __align__(16) float g_ald2[NN];
__device__ __align__(16) float g_ex2[ET];
__device__ __align__(16) float g_sum2[NN];
__device__ __align__(16) float g_h2[NN * 64];
__device__ __align__(16) float g_P[NN * 384];
__device__ __align__(16) float g_Q[NN * 384];
__device__ __align__(16) float g_h0[(size_t)EE * 128];
__device__ __align__(16) float g_h1s[(size_t)EE * 128];
__device__ __align__(16) float g_dec1[(size_t)EE * 64];

// bf16 weight images [384][128] row-major:
// [0]=Whh0 hi, [1]=Whh0 lo, [2]=Wih1 hi, [3]=Wih1 lo, [4]=Whh1 hi, [5]=Whh1 lo
#define W_ELEMS (384 * 128)
__device__ __align__(16) __nv_bfloat16 g_wimg[6][W_ELEMS];

// ---------------- packed fp32x2 helpers (sm_103a FFMA2) ------------
__device__ __forceinline__ ull dup2(float x) {
    ull r;
    unsigned u = __float_as_uint(x);
    asm("mov.b64 %0, {%1, %1};" : "=l"(r) : "r"(u));
    return r;
}
__device__ __forceinline__ ull ffma2(ull a, ull b, ull c) {
    ull d;
    asm("fma.rn.f32x2 %0, %1, %2, %3;" : "=l"(d) : "l"(a), "l"(b), "l"(c));
    return d;
}

__device__ __forceinline__ uint32_t smem_u32(const void* p) {
    uint32_t a;
    asm("{ .reg .u64 t; cvta.to.shared.u64 t, %1; cvt.u32.u64 %0, t; }" : "=r"(a) : "l"(p));
    return a;
}
__device__ __forceinline__ float sigf(float x) { return 1.f / (1.f + expf(-x)); }

// ---------------- mma.sync helpers (family-portable: sm_80+) ------------
__device__ __forceinline__ void ldsm4(uint32_t* r, uint32_t addr) {
    asm volatile("ldmatrix.sync.aligned.m8n8.x4.shared.b16 {%0,%1,%2,%3}, [%4];"
        : "=r"(r[0]), "=r"(r[1]), "=r"(r[2]), "=r"(r[3]) : "r"(addr));
}
__device__ __forceinline__ void mma_bf16(float* c, const uint32_t* a, uint32_t b0, uint32_t b1) {
    asm volatile("mma.sync.aligned.m16n8k16.row.col.f32.bf16.bf16.f32 "
        "{%0,%1,%2,%3}, {%4,%5,%6,%7}, {%8,%9}, {%0,%1,%2,%3};"
        : "+f"(c[0]), "+f"(c[1]), "+f"(c[2]), "+f"(c[3])
        : "r"(a[0]), "r"(a[1]), "r"(a[2]), "r"(a[3]), "r"(b0), "r"(b1));
}

// Shared building blocks: A tiles 64 rows x 128 k, SMEM row stride 272 B (136 bf16, pad)
__device__ __forceinline__ void copy_b_chunk(char* sm, int off, const uint4* __restrict__ src,
                                             int tid)
{
#pragma unroll
    for (int rep = 0; rep < 8; rep++) {
        int i = rep * 256 + tid;
        int n = i >> 4, seg = i & 15;
        *(uint4*)(sm + off + n * 272 + seg * 16) = src[i];
    }
}

__device__ __forceinline__ void load_a_split(char* sm, int offHi, int offLo,
                                             const float* __restrict__ A, int m0, int tid)
{
    const float4* Ap = (const float4*)(A + (size_t)m0 * 128);
#pragma unroll
    for (int rep = 0; rep < 8; rep++) {
        int flat = rep * 256 + tid;
        float4 v = Ap[flat];
        int m = flat >> 5, k = (flat & 31) << 2;
        __nv_bfloat162 h01 = __float22bfloat162_rn(make_float2(v.x, v.y));
        __nv_bfloat162 h23 = __float22bfloat162_rn(make_float2(v.z, v.w));
        float2 f01 = __bfloat1622float2(h01);
        float2 f23 = __bfloat1622float2(h23);
        __nv_bfloat162 l01 = __float22bfloat162_rn(make_float2(v.x - f01.x, v.y - f01.y));
        __nv_bfloat162 l23 = __float22bfloat162_rn(make_float2(v.z - f23.x, v.w - f23.y));
        int doff = m * 272 + k * 2;
        *(uint2*)(sm + offHi + doff) = make_uint2(*(unsigned*)&h01, *(unsigned*)&h23);
        *(uint2*)(sm + offLo + doff) = make_uint2(*(unsigned*)&l01, *(unsigned*)&l23);
    }
}

// 3-pass bf16 split MMA over K=128 (8 ksteps): acc += Ahi*Bhi + Alo*Bhi + Ahi*Blo
__device__ __forceinline__ void mma_3pass(float acc[2][4][4],
    uint32_t aHi, uint32_t aLo, uint32_t bHi, uint32_t bLo)
{
#pragma unroll 1
    for (int pass = 0; pass < 3; pass++) {
        const uint32_t aa = (pass == 1) ? aLo : aHi;
        const uint32_t bb = (pass == 2) ? bLo : bHi;
#pragma unroll
        for (int ks = 0; ks < 8; ks++) {
            uint32_t af[2][4], bf[2][4];
            ldsm4(af[0], aa + ks * 32);
            ldsm4(af[1], aa + 4352 + ks * 32);
            ldsm4(bf[0], bb + ks * 32);
            ldsm4(bf[1], bb + 4352 + ks * 32);
#pragma unroll
            for (int mf = 0; mf < 2; mf++)
#pragma unroll
                for (int nf = 0; nf < 4; nf++)
                    mma_bf16(acc[mf][nf], af[mf],
                             bf[nf >> 1][(nf & 1) * 2], bf[nf >> 1][(nf & 1) * 2 + 1]);
        }
    }
}

#define ZERO_ACC(a) do { \
_Pragma("unroll") for (int _i = 0; _i < 2; _i++) \
_Pragma("unroll") for (int _j = 0; _j < 4; _j++) \
_Pragma("unroll") for (int _q = 0; _q < 4; _q++) (a)[_i][_j][_q] = 0.f; } while (0)

// -------- one-time weight conversion: fp32 [384,128] -> bf16 hi/lo images --------
__global__ void conv_w_kernel(const float* __restrict__ W, __nv_bfloat16* __restrict__ hi,
                              __nv_bfloat16* __restrict__ lo)
{
    int idx = blockIdx.x * blockDim.x + threadIdx.x;
    if (idx >= W_ELEMS) return;
    float v = W[idx];
    __nv_bfloat16 h = __float2bfloat16_rn(v);
    hi[idx] = h;
    lo[idx] = __float2bfloat16_rn(v - __bfloat162float(h));
}

// ============================================================================
// Fused GRU layer 0: h0 = GRU(P[src]+Q[dst] as gi, h0) — no gi/gh materialization
// ============================================================================
#define F0_AHI 0
#define F0_ALO 17408
#define F0_BHI 34816
#define F0_BLO 69632
#define F0_SRC 104448
#define F0_DST 104704
#define F0_SMEM 104960

__global__ void __launch_bounds__(256) gru0_fused_kernel(
    const int* __restrict__ ei, const float* __restrict__ P, const float* __restrict__ Q,
    float* __restrict__ h0, const uint4* __restrict__ Bh_hi, const uint4* __restrict__ Bh_lo,
    const float* __restrict__ bhh)
{
    extern __shared__ char sm[];
    const int tid = threadIdx.x, lane = tid & 31, warp = tid >> 5;
    const int m0 = blockIdx.x * 64;
    const int wm = (warp >> 2) * 32, wn = (warp & 3) * 32;
    const int g = lane >> 2, t = lane & 3;

    load_a_split(sm, F0_AHI, F0_ALO, h0, m0, tid);
    if (tid < 64) {
        ((int*)(sm + F0_SRC))[tid] = ei[m0 + tid];
        ((int*)(sm + F0_DST))[tid] = ei[EE + m0 + tid];
    }
    const int* src_sm = (const int*)(sm + F0_SRC);
    const int* dst_sm = (const int*)(sm + F0_DST);

    const uint32_t sb = smem_u32(sm);
    const uint32_t alo_o = (uint32_t)((wm + (lane & 15)) * 272 + ((lane >> 4) << 4));
    const uint32_t blo_o = (uint32_t)((wn + (lane & 7) + ((lane >> 4) << 3)) * 272
                                      + (((lane >> 3) & 1) << 4));
    const uint32_t ah = sb + F0_AHI + alo_o, al = sb + F0_ALO + alo_o;
    const uint32_t bh_s = sb + F0_BHI + blo_o, bl_s = sb + F0_BLO + blo_o;

    float zf[2][4][4], rf[2][4][4], acc[2][4][4];

    // ---- stage Z (weight chunk 1) ----
    __syncthreads();
    copy_b_chunk(sm, F0_BHI, Bh_hi + 2048, tid);
    copy_b_chunk(sm, F0_BLO, Bh_lo + 2048, tid);
    __syncthreads();
    ZERO_ACC(zf);
    mma_3pass(zf, ah, al, bh_s, bl_s);
#pragma unroll
    for (int mf = 0; mf < 2; mf++)
#pragma unroll
        for (int sub = 0; sub < 2; sub++) {
            int rowl = wm + mf * 16 + g + sub * 8;
            const float* Pr = P + (size_t)src_sm[rowl] * 384 + 128;
            const float* Qr = Q + (size_t)dst_sm[rowl] * 384 + 128;
#pragma unroll
            for (int nf = 0; nf < 4; nf++) {
                int c = wn + nf * 8 + t * 2;
                float2 pv = *(const float2*)(Pr + c);
                float2 qv = *(const float2*)(Qr + c);
                float2 b2 = *(const float2*)(bhh + 128 + c);
                int q = sub * 2;
                zf[mf][nf][q]     = sigf(zf[mf][nf][q]     + pv.x + qv.x + b2.x);
                zf[mf][nf][q + 1] = sigf(zf[mf][nf][q + 1] + pv.y + qv.y + b2.y);
            }
        }

    // ---- stage R (weight chunk 0) ----
    __syncthreads();
    copy_b_chunk(sm, F0_BHI, Bh_hi, tid);
    copy_b_chunk(sm, F0_BLO, Bh_lo, tid);
    __syncthreads();
    ZERO_ACC(rf);
    mma_3pass(rf, ah, al, bh_s, bl_s);
#pragma unroll
    for (int mf = 0; mf < 2; mf++)
#pragma unroll
        for (int sub = 0; sub < 2; sub++) {
            int rowl = wm + mf * 16 + g + sub * 8;
            const float* Pr = P + (size_t)src_sm[rowl] * 384;
            const float* Qr = Q + (size_t)dst_sm[rowl] * 384;
#pragma unroll
            for (int nf = 0; nf < 4; nf++) {
                int c = wn + nf * 8 + t * 2;
                float2 pv = *(const float2*)(Pr + c);
                float2 qv = *(const float2*)(Qr + c);
                float2 b2 = *(const float2*)(bhh + c);
                int q = sub * 2;
                rf[mf][nf][q]     = sigf(rf[mf][nf][q]     + pv.x + qv.x + b2.x);
                rf[mf][nf][q + 1] = sigf(rf[mf][nf][q + 1] + pv.y + qv.y + b2.y);
            }
        }

    // ---- stage N (weight chunk 2) + blend + store ----
    __syncthreads();
    copy_b_chunk(sm, F0_BHI, Bh_hi + 2 * 2048, tid);
    copy_b_chunk(sm, F0_BLO, Bh_lo + 2 * 2048, tid);
    __syncthreads();
    ZERO_ACC(acc);
    mma_3pass(acc, ah, al, bh_s, bl_s);
#pragma unroll
    for (int mf = 0; mf < 2; mf++)
#pragma unroll
        for (int sub = 0; sub < 2; sub++) {
            int rowl = wm + mf * 16 + g + sub * 8;
            const float* Pr = P + (size_t)src_sm[rowl] * 384 + 256;
            const float* Qr = Q + (size_t)dst_sm[rowl] * 384 + 256;
#pragma unroll
            for (int nf = 0; nf < 4; nf++) {
                int c = wn + nf * 8 + t * 2;
                float2 pv = *(const float2*)(Pr + c);
                float2 qv = *(const float2*)(Qr + c);
                float2 b2 = *(const float2*)(bhh + 256 + c);
                int q = sub * 2;
                float n0 = tanhf(pv.x + qv.x + rf[mf][nf][q]     * (acc[mf][nf][q]     + b2.x));
                float n1 = tanhf(pv.y + qv.y + rf[mf][nf][q + 1] * (acc[mf][nf][q + 1] + b2.y));
                unsigned hh = *(unsigned*)(sm + F0_AHI + rowl * 272 + c * 2);
                unsigned ll = *(unsigned*)(sm + F0_ALO + rowl * 272 + c * 2);
                float hp0 = __uint_as_float(hh << 16) + __uint_as_float(ll << 16);
                float hp1 = __uint_as_float(hh & 0xffff0000u) + __uint_as_float(ll & 0xffff0000u);
                float z0 = zf[mf][nf][q], z1 = zf[mf][nf][q + 1];
                float2 o = make_float2((1.f - z0) * n0 + z0 * hp0,
                                       (1.f - z1) * n1 + z1 * hp1);
                *(float2*)(h0 + (size_t)(m0 + rowl) * 128 + c) = o;
            }
        }
}

// ============================================================================
// Fused GRU layer 1: h1s = GRU(h0, h1s) — gi and gh both via MMA, fused gates
// ============================================================================
#define F1_A0HI 0
#define F1_A0LO 17408
#define F1_A1HI 34816
#define F1_A1LO 52224
#define F1_BIHI 69632
#define F1_BILO 104448
#define F1_BHHI 139264
#define F1_BHLO 174080
#define F1_SMEM 208896

__global__ void __launch_bounds__(256) gru1_fused_kernel(
    const float* __restrict__ h0, float* __restrict__ h1s,
    const uint4* __restrict__ Bi_hi, const uint4* __restrict__ Bi_lo,
    const uint4* __restrict__ Bh_hi, const uint4* __restrict__ Bh_lo,
    const float* __restrict__ bih, const float* __restrict__ bhh)
{
    extern __shared__ char sm[];
    const int tid = threadIdx.x, lane = tid & 31, warp = tid >> 5;
    const int m0 = blockIdx.x * 64;
    const int wm = (warp >> 2) * 32, wn = (warp & 3) * 32;
    const int g = lane >> 2, t = lane & 3;

    load_a_split(sm, F1_A0HI, F1_A0LO, h0, m0, tid);
    load_a_split(sm, F1_A1HI, F1_A1LO, h1s, m0, tid);

    const uint32_t sb = smem_u32(sm);
    const uint32_t alo_o = (uint32_t)((wm + (lane & 15)) * 272 + ((lane >> 4) << 4));
    const uint32_t blo_o = (uint32_t)((wn + (lane & 7) + ((lane >> 4) << 3)) * 272
                                      + (((lane >> 3) & 1) << 4));
    const uint32_t a0h = sb + F1_A0HI + alo_o, a0l = sb + F1_A0LO + alo_o;
    const uint32_t a1h = sb + F1_A1HI + alo_o, a1l = sb + F1_A1LO + alo_o;
    const uint32_t bi_h = sb + F1_BIHI + blo_o, bi_l = sb + F1_BILO + blo_o;
    const uint32_t bh_h = sb + F1_BHHI + blo_o, bh_l = sb + F1_BHLO + blo_o;

    float zf[2][4][4], rf[2][4][4], acc[2][4][4];

    // ---- stage Z (chunk 1) ----
    __syncthreads();
    copy_b_chunk(sm, F1_BIHI, Bi_hi + 2048, tid);
    copy_b_chunk(sm, F1_BILO, Bi_lo + 2048, tid);
    copy_b_chunk(sm, F1_BHHI, Bh_hi + 2048, tid);
    copy_b_chunk(sm, F1_BHLO, Bh_lo + 2048, tid);
    __syncthreads();
    ZERO_ACC(zf);
    mma_3pass(zf, a0h, a0l, bi_h, bi_l);
    mma_3pass(zf, a1h, a1l, bh_h, bh_l);
#pragma unroll
    for (int nf = 0; nf < 4; nf++) {
        int c = wn + nf * 8 + t * 2;
        float2 bi2 = *(const float2*)(bih + 128 + c);
        float2 bh2 = *(const float2*)(bhh + 128 + c);
        float bx = bi2.x + bh2.x, by = bi2.y + bh2.y;
#pragma unroll
        for (int mf = 0; mf < 2; mf++) {
            zf[mf][nf][0] = sigf(zf[mf][nf][0] + bx);
            zf[mf][nf][1] = sigf(zf[mf][nf][1] + by);
            zf[mf][nf][2] = sigf(zf[mf][nf][2] + bx);
            zf[mf][nf][3] = sigf(zf[mf][nf][3] + by);
        }
    }

    // ---- stage R (chunk 0) ----
    __syncthreads();
    copy_b_chunk(sm, F1_BIHI, Bi_hi, tid);
    copy_b_chunk(sm, F1_BILO, Bi_lo, tid);
    copy_b_chunk(sm, F1_BHHI, Bh_hi, tid);
    copy_b_chunk(sm, F1_BHLO, Bh_lo, tid);
    __syncthreads();
    ZERO_ACC(rf);
    mma_3pass(rf, a0h, a0l, bi_h, bi_l);
    mma_3pass(rf, a1h, a1l, bh_h, bh_l);
#pragma unroll
    for (int nf = 0; nf < 4; nf++) {
        int c = wn + nf * 8 + t * 2;
        float2 bi2 = *(const float2*)(bih + c);
        float2 bh2 = *(const float2*)(bhh + c);
        float bx = bi2.x + bh2.x, by = bi2.y + bh2.y;
#pragma unroll
        for (int mf = 0; mf < 2; mf++) {
            rf[mf][nf][0] = sigf(rf[mf][nf][0] + bx);
            rf[mf][nf][1] = sigf(rf[mf][nf][1] + by);
            rf[mf][nf][2] = sigf(rf[mf][nf][2] + bx);
            rf[mf][nf][3] = sigf(rf[mf][nf][3] + by);
        }
    }

    // ---- stage N (chunk 2): hn first, transform by r, then accumulate inn ----
    __syncthreads();
    copy_b_chunk(sm, F1_BIHI, Bi_hi + 2 * 2048, tid);
    copy_b_chunk(sm, F1_BILO, Bi_lo + 2 * 2048, tid);
    copy_b_chunk(sm, F1_BHHI, Bh_hi + 2 * 2048, tid);
    copy_b_chunk(sm, F1_BHLO, Bh_lo + 2 * 2048, tid);
    __syncthreads();
    ZERO_ACC(acc);
    mma_3pass(acc, a1h, a1l, bh_h, bh_l);      // hn (no bias yet)
#pragma unroll
    for (int nf = 0; nf < 4; nf++) {
        int c = wn + nf * 8 + t * 2;
        float2 b2 = *(const float2*)(bhh + 256 + c);
#pragma unroll
        for (int mf = 0; mf < 2; mf++) {
            acc[mf][nf][0] = rf[mf][nf][0] * (acc[mf][nf][0] + b2.x);
            acc[mf][nf][1] = rf[mf][nf][1] * (acc[mf][nf][1] + b2.y);
            acc[mf][nf][2] = rf[mf][nf][2] * (acc[mf][nf][2] + b2.x);
            acc[mf][nf][3] = rf[mf][nf][3] * (acc[mf][nf][3] + b2.y);
        }
    }
    mma_3pass(acc, a0h, a0l, bi_h, bi_l);      // += inn

    // ---- epilogue: n = tanh(acc + bih_n); h = (1-z)*n + z*hprev ----
#pragma unroll
    for (int nf = 0; nf < 4; nf++) {
        int c = wn + nf * 8 + t * 2;
        float2 bi2 = *(const float2*)(bih + 256 + c);
#pragma unroll
        for (int mf = 0; mf < 2; mf++)
#pragma unroll
            for (int sub = 0; sub < 2; sub++) {
                int rowl = wm + mf * 16 + g + sub * 8;
                int q = sub * 2;
                float n0 = tanhf(acc[mf][nf][q]     + bi2.x);
                float n1 = tanhf(acc[mf][nf][q + 1] + bi2.y);
                unsigned hh = *(unsigned*)(sm + F1_A1HI + rowl * 272 + c * 2);
                unsigned ll = *(unsigned*)(sm + F1_A1LO + rowl * 272 + c * 2);
                float hp0 = __uint_as_float(hh << 16) + __uint_as_float(ll << 16);
                float hp1 = __uint_as_float(hh & 0xffff0000u) + __uint_as_float(ll & 0xffff0000u);
                float z0 = zf[mf][nf][q], z1 = zf[mf][nf][q + 1];
                float2 o = make_float2((1.f - z0) * n0 + z0 * hp0,
                                       (1.f - z1) * n1 + z1 * hp1);
                *(float2*)(h1s + (size_t)(m0 + rowl) * 128 + c) = o;
            }
    }
}

// ---------------- scalar FFMA2 GEMM (small GEMMs): C = A * B (+bias) ------------
template <bool B_NK, bool RELU>
__global__ void __launch_bounds__(256) sgemm_kernel(
    const float* __restrict__ A, const float* __restrict__ B,
    const float* __restrict__ bias, float* __restrict__ C,
    int M, int K, int ldb, int ldc)
{
    __shared__ float As[16][128];
    __shared__ float Bs[16][64];
    const int tid = threadIdx.x;
    const int m0 = blockIdx.x * 128;
    const int n0 = blockIdx.y * 64;
    const int tx = tid & 15;
    const int ty = tid >> 4;

    ull acc[4][4];
#pragma unroll
    for (int i = 0; i < 4; i++)
#pragma unroll
        for (int j = 0; j < 4; j++) acc[i][j] = 0ULL;

    const int ar = tid >> 2;
    const int ac = (tid & 3) << 2;
    const int nIter = K >> 4;

    for (int it = 0; it < nIter; ++it) {
        const int k0 = it << 4;
#pragma unroll
        for (int half = 0; half < 2; ++half) {
            int row = ar + half * 64;
            float4 v = make_float4(0.f, 0.f, 0.f, 0.f);
            if (m0 + row < M)
                v = *reinterpret_cast<const float4*>(A + (size_t)(m0 + row) * K + k0 + ac);
            As[ac + 0][row] = v.x; As[ac + 1][row] = v.y;
            As[ac + 2][row] = v.z; As[ac + 3][row] = v.w;
        }
        if (B_NK) {
            int n = tid >> 2;
            float4 v = *reinterpret_cast<const float4*>(B + (size_t)(n0 + n) * ldb + k0 + ac);
            Bs[ac + 0][n] = v.x; Bs[ac + 1][n] = v.y;
            Bs[ac + 2][n] = v.z; Bs[ac + 3][n] = v.w;
        } else {
            int kk = tid >> 4;
            int nn = (tid & 15) << 2;
            *reinterpret_cast<float4*>(&Bs[kk][nn]) =
                *reinterpret_cast<const float4*>(B + (size_t)(k0 + kk) * ldb + n0 + nn);
        }
        __syncthreads();
#pragma unroll
        for (int kk = 0; kk < 16; ++kk) {
            ulonglong2 aA = *reinterpret_cast<const ulonglong2*>(&As[kk][ty * 8]);
            ulonglong2 aB = *reinterpret_cast<const ulonglong2*>(&As[kk][ty * 8 + 4]);
            float4 b = *reinterpret_cast<const float4*>(&Bs[kk][tx * 4]);
            ull am0 = aA.x, am1 = aA.y, am2 = aB.x, am3 = aB.y;
            ull bb0 = dup2(b.x), bb1 = dup2(b.y), bb2 = dup2(b.z), bb3 = dup2(b.w);
            acc[0][0] = ffma2(am0, bb0, acc[0][0]); acc[0][1] = ffma2(am0, bb1, acc[0][1]);
            acc[0][2] = ffma2(am0, bb2, acc[0][2]); acc[0][3] = ffma2(am0, bb3, acc[0][3]);
            acc[1][0] = ffma2(am1, bb0, acc[1][0]); acc[1][1] = ffma2(am1, bb1, acc[1][1]);
            acc[1][2] = ffma2(am1, bb2, acc[1][2]); acc[1][3] = ffma2(am1, bb3, acc[1][3]);
            acc[2][0] = ffma2(am2, bb0, acc[2][0]); acc[2][1] = ffma2(am2, bb1, acc[2][1]);
            acc[2][2] = ffma2(am2, bb2, acc[2][2]); acc[2][3] = ffma2(am2, bb3, acc[2][3]);
            acc[3][0] = ffma2(am3, bb0, acc[3][0]); acc[3][1] = ffma2(am3, bb1, acc[3][1]);
            acc[3][2] = ffma2(am3, bb2, acc[3][2]); acc[3][3] = ffma2(am3, bb3, acc[3][3]);
        }
        __syncthreads();
    }

    float4 bv = make_float4(0.f, 0.f, 0.f, 0.f);
    if (bias) bv = *reinterpret_cast<const float4*>(bias + n0 + tx * 4);
#pragma unroll
    for (int i = 0; i < 4; i++) {
        float lo[4], hi[4];
#pragma unroll
        for (int j = 0; j < 4; j++) {
            lo[j] = __uint_as_float((unsigned)(acc[i][j] & 0xffffffffULL));
            hi[j] = __uint_as_float((unsigned)(acc[i][j] >> 32));
        }
        float4 ce = make_float4(lo[0] + bv.x, lo[1] + bv.y, lo[2] + bv.z, lo[3] + bv.w);
        float4 co = make_float4(hi[0] + bv.x, hi[1] + bv.y, hi[2] + bv.z, hi[3] + bv.w);
        if (RELU) {
            ce.x = fmaxf(ce.x, 0.f); ce.y = fmaxf(ce.y, 0.f);
            ce.z = fmaxf(ce.z, 0.f); ce.w = fmaxf(ce.w, 0.f);
            co.x = fmaxf(co.x, 0.f); co.y = fmaxf(co.y, 0.f);
            co.z = fmaxf(co.z, 0.f); co.w = fmaxf(co.w, 0.f);
        }
        int m = m0 + ty * 8 + i * 2;
        if (m < M)
            *reinterpret_cast<float4*>(C + (size_t)m * ldc + n0 + tx * 4) = ce;
        if (m + 1 < M)
            *reinterpret_cast<float4*>(C + (size_t)(m + 1) * ldc + n0 + tx * 4) = co;
    }
}

// ---------------- GAT attention logits ------------
__global__ void alpha4_kernel(const float* __restrict__ h, const float* __restrict__ av,
                              const float* __restrict__ dv, float* __restrict__ als,
                              float* __restrict__ ald)
{
    int idx = blockIdx.x * blockDim.x + threadIdx.x;
    if (idx >= NN * 4) return;
    int i = idx >> 2, hh = idx & 3;
    const float* hp = h + (size_t)i * 256 + hh * 64;
    const float* ap = av + hh * 64;
    const float* dp = dv + hh * 64;
    float ss = 0.f, sd = 0.f;
#pragma unroll
    for (int c = 0; c < 64; c++) { float v = hp[c]; ss += v * ap[c]; sd += v * dp[c]; }
    als[idx] = ss; ald[idx] = sd;
}

__global__ void alpha1_kernel(const float* __restrict__ h, const float* __restrict__ av,
                              const float* __restrict__ dv, float* __restrict__ als,
                              float* __restrict__ ald)
{
    int i = blockIdx.x * blockDim.x + threadIdx.x;
    if (i >= NN) return;
    const float* hp = h + (size_t)i * 64;
    float ss = 0.f, sd = 0.f;
#pragma unroll
    for (int c = 0; c < 64; c++) { float v = hp[c]; ss += v * av[c]; sd += v * dv[c]; }
    als[i] = ss; ald[i] = sd;
}

// ---------------- edge softmax numerator + denominator ------------
template <int H>
__global__ void edge_exp_kernel(const int* __restrict__ ei, const float* __restrict__ als,
                                const float* __restrict__ ald, float* __restrict__ exbuf,
                                float* __restrict__ sums)
{
    int idx = blockIdx.x * blockDim.x + threadIdx.x;
    if (idx >= ET * H) return;
    int k = idx / H, hh = idx % H;
    int s, d;
    if (k < EE) { s = ei[k]; d = ei[EE + k]; } else { s = k - EE; d = s; }
    float e = als[s * H + hh] + ald[d * H + hh];
    e = (e >= 0.f) ? e : 0.2f * e;
    float ex = expf(e);
    exbuf[(size_t)k * H + hh] = ex;
    atomicAdd(&sums[d * H + hh], ex);
}

// ---------------- weighted scatter aggregation ------------
template <int HC, int C>
__global__ void edge_agg_kernel(const int* __restrict__ ei, const float* __restrict__ hlin,
                                const float* __restrict__ exbuf, const float* __restrict__ sums,
                                float* __restrict__ outp)
{
    int idx = blockIdx.x * blockDim.x + threadIdx.x;
    if (idx >= ET * HC) return;
    int k = idx / HC, r = idx % HC;
    constexpr int H = HC / C;
    int hh = r / C;
    int s, d;
    if (k < EE) { s = ei[k]; d = ei[EE + k]; } else { s = k - EE; d = s; }
    float att = exbuf[(size_t)k * H + hh] / (sums[d * H + hh] + 1e-16f);
    atomicAdd(&outp[(size_t)d * HC + r], hlin[(size_t)s * HC + r] * att);
}

// ---------------- pointwise ------------
__global__ void elu_bias_kernel(float* __restrict__ x, const float* __restrict__ b, int total, int C)
{
    int i = blockIdx.x * blockDim.x + threadIdx.x;
    if (i >= total) return;
    float v = x[i] + b[i % C];
    x[i] = (v > 0.f) ? v : expm1f(v);
}
__global__ void bias_kernel(float* __restrict__ x, const float* __restrict__ b, int total, int C)
{
    int i = blockIdx.x * blockDim.x + threadIdx.x;
    if (i >= total) return;
    x[i] += b[i % C];
}

// ---------------- decoder stage 2 ------------
__global__ void decoder2_kernel(const float* __restrict__ d1, const float* __restrict__ Wd2,
                                const float* __restrict__ bd2, float* __restrict__ out)
{
    int e = blockIdx.x * blockDim.x + threadIdx.x;
    if (e >= EE) return;
    const float* r = d1 + (size_t)e * 64;
    float s = 0.f;
#pragma unroll
    for (int c = 0; c < 64; c++) s += r[c] * Wd2[c];
    out[e] = s + bd2[0];
}

// ---------------- host orchestration ------------
static inline dim3 ggrid(int M, int Ntot) { return dim3((M + 127) / 128, Ntot / 64); }
static inline int gb(int n) { return (n + 255) / 256; }

extern "C" void kernel_launch(void* const* d_in, const int* in_sizes, int n_in,
                              void* d_out, int out_size)
{
    (void)in_sizes; (void)n_in; (void)out_size;
    const float* x_seq  = (const float*)d_in[0];
    const int*   ei     = (const int*)d_in[1];
    const float* W1     = (const float*)d_in[2];
    const float* a_src1 = (const float*)d_in[3];
    const float* a_dst1 = (const float*)d_in[4];
    const float* b1     = (const float*)d_in[5];
    const float* W2     = (const float*)d_in[6];
    const float* a_src2 = (const float*)d_in[7];
    const float* a_dst2 = (const float*)d_in[8];
    const float* b2     = (const float*)d_in[9];
    const float* Wih0   = (const float*)d_in[10];
    const float* Whh0   = (const float*)d_in[11];
    const float* bih0   = (const float*)d_in[12];
    const float* bhh0   = (const float*)d_in[13];
    const float* Wih1   = (const float*)d_in[14];
    const float* Whh1   = (const float*)d_in[15];
    const float* bih1   = (const float*)d_in[16];
    const float* bhh1   = (const float*)d_in[17];
    const float* Wd1    = (const float*)d_in[18];
    const float* bd1    = (const float*)d_in[19];
    const float* Wd2    = (const float*)d_in[20];
    const float* bd2    = (const float*)d_in[21];
    float* out = (float*)d_out;

    float *p_h1lin, *p_als1, *p_ald1, *p_ex1, *p_sum1, *p_out1;
    float *p_h2lin, *p_als2, *p_ald2, *p_ex2, *p_sum2, *p_h2;
    float *p_P, *p_Q, *p_h0, *p_h1s, *p_dec1;
    __nv_bfloat16* p_wimg;
    cudaGetSymbolAddress((void**)&p_h1lin, g_h1lin);
    cudaGetSymbolAddress((void**)&p_als1, g_als1);
    cudaGetSymbolAddress((void**)&p_ald1, g_ald1);
    cudaGetSymbolAddress((void**)&p_ex1, g_ex1);
    cudaGetSymbolAddress((void**)&p_sum1, g_sum1);
    cudaGetSymbolAddress((void**)&p_out1, g_out1);
    cudaGetSymbolAddress((void**)&p_h2lin, g_h2lin);
    cudaGetSymbolAddress((void**)&p_als2, g_als2);
    cudaGetSymbolAddress((void**)&p_ald2, g_ald2);
    cudaGetSymbolAddress((void**)&p_ex2, g_ex2);
    cudaGetSymbolAddress((void**)&p_sum2, g_sum2);
    cudaGetSymbolAddress((void**)&p_h2, g_h2);
    cudaGetSymbolAddress((void**)&p_P, g_P);
    cudaGetSymbolAddress((void**)&p_Q, g_Q);
    cudaGetSymbolAddress((void**)&p_h0, g_h0);
    cudaGetSymbolAddress((void**)&p_h1s, g_h1s);
    cudaGetSymbolAddress((void**)&p_dec1, g_dec1);
    cudaGetSymbolAddress((void**)&p_wimg, g_wimg);

    cudaFuncSetAttribute(gru0_fused_kernel, cudaFuncAttributeMaxDynamicSharedMemorySize, F0_SMEM);
    cudaFuncSetAttribute(gru1_fused_kernel, cudaFuncAttributeMaxDynamicSharedMemorySize, F1_SMEM);

    const __nv_bfloat16* whh0h = p_wimg + 0 * W_ELEMS;
    const __nv_bfloat16* whh0l = p_wimg + 1 * W_ELEMS;
    const __nv_bfloat16* wih1h = p_wimg + 2 * W_ELEMS;
    const __nv_bfloat16* wih1l = p_wimg + 3 * W_ELEMS;
    const __nv_bfloat16* whh1h = p_wimg + 4 * W_ELEMS;
    const __nv_bfloat16* whh1l = p_wimg + 5 * W_ELEMS;

    // reset recurrent state every call
    cudaMemsetAsync(p_h0, 0, (size_t)EE * 128 * sizeof(float), 0);
    cudaMemsetAsync(p_h1s, 0, (size_t)EE * 128 * sizeof(float), 0);

    // weight conversion to bf16 hi/lo images
    conv_w_kernel<<<gb(W_ELEMS), 256>>>(Whh0, (__nv_bfloat16*)whh0h, (__nv_bfloat16*)whh0l);
    conv_w_kernel<<<gb(W_ELEMS), 256>>>(Wih1, (__nv_bfloat16*)wih1h, (__nv_bfloat16*)wih1l);
    conv_w_kernel<<<gb(W_ELEMS), 256>>>(Whh1, (__nv_bfloat16*)whh1h, (__nv_bfloat16*)whh1l);

    for (int t = 0; t < T_STEPS; ++t) {
        const float* x_t = x_seq + (size_t)t * NN * 32;

        // ---- GAT layer 1 ----
        cudaMemsetAsync(p_out1, 0, (size_t)NN * 256 * sizeof(float), 0);
        cudaMemsetAsync(p_sum1, 0, (size_t)NN * 4 * sizeof(float), 0);
        sgemm_kernel<false, false><<<ggrid(NN, 256), 256>>>(x_t, W1, nullptr, p_h1lin,
                                                            NN, 32, 256, 256);
        alpha4_kernel<<<gb(NN * 4), 256>>>(p_h1lin, a_src1, a_dst1, p_als1, p_ald1);
        edge_exp_kernel<4><<<gb(ET * 4), 256>>>(ei, p_als1, p_ald1, p_ex1, p_sum1);
        edge_agg_kernel<256, 64><<<gb(ET * 256), 256>>>(ei, p_h1lin, p_ex1, p_sum1, p_out1);
        elu_bias_kernel<<<gb(NN * 256), 256>>>(p_out1, b1, NN * 256, 256);

        // ---- GAT layer 2 ----
        cudaMemsetAsync(p_h2, 0, (size_t)NN * 64 * sizeof(float), 0);
        cudaMemsetAsync(p_sum2, 0, (size_t)NN * sizeof(float), 0);
        sgemm_kernel<false, false><<<ggrid(NN, 64), 256>>>(p_out1, W2, nullptr, p_h2lin,
                                                           NN, 256, 64, 64);
        alpha1_kernel<<<gb(NN), 256>>>(p_h2lin, a_src2, a_dst2, p_als2, p_ald2);
        edge_exp_kernel<1><<<gb(ET), 256>>>(ei, p_als2, p_ald2, p_ex2, p_sum2);
        edge_agg_kernel<64, 64><<<gb(ET * 64), 256>>>(ei, p_h2lin, p_ex2, p_sum2, p_h2);
        bias_kernel<<<gb(NN * 64), 256>>>(p_h2, b2, NN * 64, 64);

        // ---- GRU layer 0: node-level P/Q, then fused GEMM+gate ----
        sgemm_kernel<true, false><<<ggrid(NN, 384), 256>>>(p_h2, Wih0, bih0, p_P,
                                                           NN, 64, 128, 384);
        sgemm_kernel<true, false><<<ggrid(NN, 384), 256>>>(p_h2, Wih0 + 64, nullptr, p_Q,
                                                           NN, 64, 128, 384);
        gru0_fused_kernel<<<EE / 64, 256, F0_SMEM>>>(ei, p_P, p_Q, p_h0,
            (const uint4*)whh0h, (const uint4*)whh0l, bhh0);

        // ---- GRU layer 1: fully fused ----
        gru1_fused_kernel<<<EE / 64, 256, F1_SMEM>>>(p_h0, p_h1s,
            (const uint4*)wih1h, (const uint4*)wih1l,
            (const uint4*)whh1h, (const uint4*)whh1l, bih1, bhh1);
    }

    // ---- decoder ----
    sgemm_kernel<false, true><<<ggrid(EE, 64), 256>>>(p_h1s, Wd1, bd1, p_dec1,
                                                      EE, 128, 64, 64);
    decoder2_kernel<<<gb(EE), 256>>>(p_dec1, Wd2, bd2, out);
}

// round 14
// speedup vs baseline: 2.1401x; 1.1997x over previous
#include <cuda_runtime.h>
#include <cuda_bf16.h>
#include <cstdint>

typedef unsigned long long ull;

#define T_STEPS 8
#define NN 20000
#define EE 320000
#define ET (EE + NN)

// ---------------- scratch (static device globals; no allocation at run time) ------------
__device__ __align__(16) float g_h1lin[NN * 256];
__device__ __align__(16) float g_als1[NN * 4];
__device__ __align__(16) float g_ald1[NN * 4];
__device__ __align__(16) float g_out1[NN * 256];
__device__ __align__(16) float g_h2lin[NN * 64];
__device__ __align__(16) float g_als2[NN];
__device__ __align__(16) float g_ald2[NN];
__device__ __align__(16) float g_h2[NN * 64];
__device__ __align__(16) float g_P[NN * 384];
__device__ __align__(16) float g_Q[NN * 384];
__device__ __align__(16) float g_h0[(size_t)EE * 128];
__device__ __align__(16) float g_h1s[(size_t)EE * 128];
__device__ __align__(16) float g_dec1[(size_t)EE * 64];

// CSR (dst-grouped incoming edges), rebuilt once per call
__device__ int g_cnt[NN];
__device__ int g_ptr[NN + 1];
__device__ int g_woff[NN];
__device__ int g_csr_src[EE];

// bf16 weight images [384][128] row-major:
// [0]=Whh0 hi, [1]=Whh0 lo, [2]=Wih1 hi, [3]=Wih1 lo, [4]=Whh1 hi, [5]=Whh1 lo
#define W_ELEMS (384 * 128)
__device__ __align__(16) __nv_bfloat16 g_wimg[6][W_ELEMS];

// ---------------- packed fp32x2 helpers (sm_103a FFMA2) ------------
__device__ __forceinline__ ull dup2(float x) {
    ull r;
    unsigned u = __float_as_uint(x);
    asm("mov.b64 %0, {%1, %1};" : "=l"(r) : "r"(u));
    return r;
}
__device__ __forceinline__ ull ffma2(ull a, ull b, ull c) {
    ull d;
    asm("fma.rn.f32x2 %0, %1, %2, %3;" : "=l"(d) : "l"(a), "l"(b), "l"(c));
    return d;
}

__device__ __forceinline__ uint32_t smem_u32(const void* p) {
    uint32_t a;
    asm("{ .reg .u64 t; cvta.to.shared.u64 t, %1; cvt.u32.u64 %0, t; }" : "=r"(a) : "l"(p));
    return a;
}
__device__ __forceinline__ float sigf(float x) { return 1.f / (1.f + expf(-x)); }
__device__ __forceinline__ float eluf(float x) { return x > 0.f ? x : expm1f(x); }
__device__ __forceinline__ float lrelu(float x) { return x >= 0.f ? x : 0.2f * x; }

// ---------------- mma.sync helpers (family-portable: sm_80+) ------------
__device__ __forceinline__ void ldsm4(uint32_t* r, uint32_t addr) {
    asm volatile("ldmatrix.sync.aligned.m8n8.x4.shared.b16 {%0,%1,%2,%3}, [%4];"
        : "=r"(r[0]), "=r"(r[1]), "=r"(r[2]), "=r"(r[3]) : "r"(addr));
}
__device__ __forceinline__ void mma_bf16(float* c, const uint32_t* a, uint32_t b0, uint32_t b1) {
    asm volatile("mma.sync.aligned.m16n8k16.row.col.f32.bf16.bf16.f32 "
        "{%0,%1,%2,%3}, {%4,%5,%6,%7}, {%8,%9}, {%0,%1,%2,%3};"
        : "+f"(c[0]), "+f"(c[1]), "+f"(c[2]), "+f"(c[3])
        : "r"(a[0]), "r"(a[1]), "r"(a[2]), "r"(a[3]), "r"(b0), "r"(b1));
}

// Shared building blocks: A tiles 64 rows x 128 k, SMEM row stride 272 B (136 bf16, pad)
__device__ __forceinline__ void copy_b_chunk(char* sm, int off, const uint4* __restrict__ src,
                                             int tid)
{
#pragma unroll
    for (int rep = 0; rep < 8; rep++) {
        int i = rep * 256 + tid;
        int n = i >> 4, seg = i & 15;
        *(uint4*)(sm + off + n * 272 + seg * 16) = src[i];
    }
}

__device__ __forceinline__ void load_a_split(char* sm, int offHi, int offLo,
                                             const float* __restrict__ A, int m0, int tid)
{
    const float4* Ap = (const float4*)(A + (size_t)m0 * 128);
#pragma unroll
    for (int rep = 0; rep < 8; rep++) {
        int flat = rep * 256 + tid;
        float4 v = Ap[flat];
        int m = flat >> 5, k = (flat & 31) << 2;
        __nv_bfloat162 h01 = __float22bfloat162_rn(make_float2(v.x, v.y));
        __nv_bfloat162 h23 = __float22bfloat162_rn(make_float2(v.z, v.w));
        float2 f01 = __bfloat1622float2(h01);
        float2 f23 = __bfloat1622float2(h23);
        __nv_bfloat162 l01 = __float22bfloat162_rn(make_float2(v.x - f01.x, v.y - f01.y));
        __nv_bfloat162 l23 = __float22bfloat162_rn(make_float2(v.z - f23.x, v.w - f23.y));
        int doff = m * 272 + k * 2;
        *(uint2*)(sm + offHi + doff) = make_uint2(*(unsigned*)&h01, *(unsigned*)&h23);
        *(uint2*)(sm + offLo + doff) = make_uint2(*(unsigned*)&l01, *(unsigned*)&l23);
    }
}

// 3-pass bf16 split MMA over K=128 (8 ksteps): acc += Ahi*Bhi + Alo*Bhi + Ahi*Blo
__device__ __forceinline__ void mma_3pass(float acc[2][4][4],
    uint32_t aHi, uint32_t aLo, uint32_t bHi, uint32_t bLo)
{
#pragma unroll 1
    for (int pass = 0; pass < 3; pass++) {
        const uint32_t aa = (pass == 1) ? aLo : aHi;
        const uint32_t bb = (pass == 2) ? bLo : bHi;
#pragma unroll
        for (int ks = 0; ks < 8; ks++) {
            uint32_t af[2][4], bf[2][4];
            ldsm4(af[0], aa + ks * 32);
            ldsm4(af[1], aa + 4352 + ks * 32);
            ldsm4(bf[0], bb + ks * 32);
            ldsm4(bf[1], bb + 4352 + ks * 32);
#pragma unroll
            for (int mf = 0; mf < 2; mf++)
#pragma unroll
                for (int nf = 0; nf < 4; nf++)
                    mma_bf16(acc[mf][nf], af[mf],
                             bf[nf >> 1][(nf & 1) * 2], bf[nf >> 1][(nf & 1) * 2 + 1]);
        }
    }
}

#define ZERO_ACC(a) do { \
_Pragma("unroll") for (int _i = 0; _i < 2; _i++) \
_Pragma("unroll") for (int _j = 0; _j < 4; _j++) \
_Pragma("unroll") for (int _q = 0; _q < 4; _q++) (a)[_i][_j][_q] = 0.f; } while (0)

// -------- one-time weight conversion: fp32 [384,128] -> bf16 hi/lo images --------
__global__ void conv_w_kernel(const float* __restrict__ W, __nv_bfloat16* __restrict__ hi,
                              __nv_bfloat16* __restrict__ lo)
{
    int idx = blockIdx.x * blockDim.x + threadIdx.x;
    if (idx >= W_ELEMS) return;
    float v = W[idx];
    __nv_bfloat16 h = __float2bfloat16_rn(v);
    hi[idx] = h;
    lo[idx] = __float2bfloat16_rn(v - __bfloat162float(h));
}

// ============================ CSR construction (once per call) ============================
__global__ void csr_count_kernel(const int* __restrict__ ei, int* __restrict__ cnt)
{
    int e = blockIdx.x * blockDim.x + threadIdx.x;
    if (e >= EE) return;
    atomicAdd(&cnt[ei[EE + e]], 1);
}

__global__ void __launch_bounds__(1024) csr_scan_kernel(
    const int* __restrict__ cnt, int* __restrict__ ptr, int* __restrict__ woff)
{
    __shared__ int part[1024];
    const int t = threadIdx.x;
    const int base = t * 20;                    // 1024*20 = 20480 >= NN
    int s = 0;
#pragma unroll
    for (int i = 0; i < 20; i++) {
        int idx = base + i;
        if (idx < NN) s += cnt[idx];
    }
    part[t] = s;
    __syncthreads();
    for (int off = 1; off < 1024; off <<= 1) {
        int v = (t >= off) ? part[t - off] : 0;
        __syncthreads();
        part[t] += v;
        __syncthreads();
    }
    int run = (t > 0) ? part[t - 1] : 0;
#pragma unroll
    for (int i = 0; i < 20; i++) {
        int idx = base + i;
        if (idx < NN) { ptr[idx] = run; woff[idx] = run; run += cnt[idx]; }
    }
    if (t == 0) ptr[NN] = part[1023];
}

__global__ void csr_scatter_kernel(const int* __restrict__ ei, int* __restrict__ woff,
                                   int* __restrict__ csr_src)
{
    int e = blockIdx.x * blockDim.x + threadIdx.x;
    if (e >= EE) return;
    int d = ei[EE + e];
    int pos = atomicAdd(&woff[d], 1);
    csr_src[pos] = ei[e];
}

// ================== GAT aggregation: warp-per-node CSR gather (no atomics) ==============
// GAT1: 4 heads x 64 ch. Lane owns 8 cols [lane*8, lane*8+8); head = lane>>3.
// out1[d] = elu( (self+edges weighted sum)/denom + b1 )
__global__ void __launch_bounds__(256) gat1_agg_kernel(
    const int* __restrict__ ptr, const int* __restrict__ csr_src,
    const float* __restrict__ hlin, const float* __restrict__ als,
    const float* __restrict__ ald, const float* __restrict__ b1,
    float* __restrict__ out1)
{
    const int node = blockIdx.x * 8 + (threadIdx.x >> 5);
    if (node >= NN) return;
    const int lane = threadIdx.x & 31;
    const int h = lane >> 3;

    const float aldv = ald[node * 4 + h];
    float den = expf(lrelu(als[node * 4 + h] + aldv));   // self loop
    const float4* hp = (const float4*)(hlin + (size_t)node * 256) + lane * 2;
    float4 s0 = hp[0], s1 = hp[1];
    float a0 = den * s0.x, a1 = den * s0.y, a2 = den * s0.z, a3 = den * s0.w;
    float a4 = den * s1.x, a5 = den * s1.y, a6 = den * s1.z, a7 = den * s1.w;

    const int end = ptr[node + 1];
    for (int j = ptr[node]; j < end; j++) {
        int s = csr_src[j];                               // warp-uniform
        float w = expf(lrelu(als[s * 4 + h] + aldv));
        den += w;
        const float4* sp = (const float4*)(hlin + (size_t)s * 256) + lane * 2;
        float4 u0 = sp[0], u1 = sp[1];
        a0 += w * u0.x; a1 += w * u0.y; a2 += w * u0.z; a3 += w * u0.w;
        a4 += w * u1.x; a5 += w * u1.y; a6 += w * u1.z; a7 += w * u1.w;
    }
    const float inv = 1.f / (den + 1e-16f);
    const float4* bp = (const float4*)b1 + lane * 2;
    float4 bv0 = bp[0], bv1 = bp[1];
    float4 o0 = make_float4(eluf(a0 * inv + bv0.x), eluf(a1 * inv + bv0.y),
                            eluf(a2 * inv + bv0.z), eluf(a3 * inv + bv0.w));
    float4 o1 = make_float4(eluf(a4 * inv + bv1.x), eluf(a5 * inv + bv1.y),
                            eluf(a6 * inv + bv1.z), eluf(a7 * inv + bv1.w));
    float4* op = (float4*)(out1 + (size_t)node * 256) + lane * 2;
    op[0] = o0; op[1] = o1;
}

// GAT2: 1 head x 64 ch. Lane owns 2 cols. h2[d] = sum/denom + b2 (no activation).
__global__ void __launch_bounds__(256) gat2_agg_kernel(
    const int* __restrict__ ptr, const int* __restrict__ csr_src,
    const float* __restrict__ hlin, const float* __restrict__ als,
    const float* __restrict__ ald, const float* __restrict__ b2,
    float* __restrict__ h2)
{
    const int node = blockIdx.x * 8 + (threadIdx.x >> 5);
    if (node >= NN) return;
    const int lane = threadIdx.x & 31;

    const float aldv = ald[node];
    float den = expf(lrelu(als[node] + aldv));            // self loop
    float2 sv = *(const float2*)(hlin + (size_t)node * 64 + lane * 2);
    float a0 = den * sv.x, a1 = den * sv.y;

    const int end = ptr[node + 1];
    for (int j = ptr[node]; j < end; j++) {
        int s = csr_src[j];
        float w = expf(lrelu(als[s] + aldv));
        den += w;
        float2 u = *(const float2*)(hlin + (size_t)s * 64 + lane * 2);
        a0 += w * u.x; a1 += w * u.y;
    }
    const float inv = 1.f / (den + 1e-16f);
    float2 bv = *(const float2*)(b2 + lane * 2);
    *(float2*)(h2 + (size_t)node * 64 + lane * 2) =
        make_float2(a0 * inv + bv.x, a1 * inv + bv.y);
}

// ============================================================================
// Fused GRU layer 0: h0 = GRU(P[src]+Q[dst] as gi, h0)
// ============================================================================
#define F0_AHI 0
#define F0_ALO 17408
#define F0_BHI 34816
#define F0_BLO 69632
#define F0_SRC 104448
#define F0_DST 104704
#define F0_SMEM 104960

__global__ void __launch_bounds__(256) gru0_fused_kernel(
    const int* __restrict__ ei, const float* __restrict__ P, const float* __restrict__ Q,
    float* __restrict__ h0, const uint4* __restrict__ Bh_hi, const uint4* __restrict__ Bh_lo,
    const float* __restrict__ bhh)
{
    extern __shared__ char sm[];
    const int tid = threadIdx.x, lane = tid & 31, warp = tid >> 5;
    const int m0 = blockIdx.x * 64;
    const int wm = (warp >> 2) * 32, wn = (warp & 3) * 32;
    const int g = lane >> 2, t = lane & 3;

    load_a_split(sm, F0_AHI, F0_ALO, h0, m0, tid);
    if (tid < 64) {
        ((int*)(sm + F0_SRC))[tid] = ei[m0 + tid];
        ((int*)(sm + F0_DST))[tid] = ei[EE + m0 + tid];
    }
    const int* src_sm = (const int*)(sm + F0_SRC);
    const int* dst_sm = (const int*)(sm + F0_DST);

    const uint32_t sb = smem_u32(sm);
    const uint32_t alo_o = (uint32_t)((wm + (lane & 15)) * 272 + ((lane >> 4) << 4));
    const uint32_t blo_o = (uint32_t)((wn + (lane & 7) + ((lane >> 4) << 3)) * 272
                                      + (((lane >> 3) & 1) << 4));
    const uint32_t ah = sb + F0_AHI + alo_o, al = sb + F0_ALO + alo_o;
    const uint32_t bh_s = sb + F0_BHI + blo_o, bl_s = sb + F0_BLO + blo_o;

    float zf[2][4][4], rf[2][4][4], acc[2][4][4];

    // ---- stage Z (weight chunk 1) ----
    __syncthreads();
    copy_b_chunk(sm, F0_BHI, Bh_hi + 2048, tid);
    copy_b_chunk(sm, F0_BLO, Bh_lo + 2048, tid);
    __syncthreads();
    ZERO_ACC(zf);
    mma_3pass(zf, ah, al, bh_s, bl_s);
#pragma unroll
    for (int mf = 0; mf < 2; mf++)
#pragma unroll
        for (int sub = 0; sub < 2; sub++) {
            int rowl = wm + mf * 16 + g + sub * 8;
            const float* Pr = P + (size_t)src_sm[rowl] * 384 + 128;
            const float* Qr = Q + (size_t)dst_sm[rowl] * 384 + 128;
#pragma unroll
            for (int nf = 0; nf < 4; nf++) {
                int c = wn + nf * 8 + t * 2;
                float2 pv = *(const float2*)(Pr + c);
                float2 qv = *(const float2*)(Qr + c);
                float2 b2 = *(const float2*)(bhh + 128 + c);
                int q = sub * 2;
                zf[mf][nf][q]     = sigf(zf[mf][nf][q]     + pv.x + qv.x + b2.x);
                zf[mf][nf][q + 1] = sigf(zf[mf][nf][q + 1] + pv.y + qv.y + b2.y);
            }
        }

    // ---- stage R (weight chunk 0) ----
    __syncthreads();
    copy_b_chunk(sm, F0_BHI, Bh_hi, tid);
    copy_b_chunk(sm, F0_BLO, Bh_lo, tid);
    __syncthreads();
    ZERO_ACC(rf);
    mma_3pass(rf, ah, al, bh_s, bl_s);
#pragma unroll
    for (int mf = 0; mf < 2; mf++)
#pragma unroll
        for (int sub = 0; sub < 2; sub++) {
            int rowl = wm + mf * 16 + g + sub * 8;
            const float* Pr = P + (size_t)src_sm[rowl] * 384;
            const float* Qr = Q + (size_t)dst_sm[rowl] * 384;
#pragma unroll
            for (int nf = 0; nf < 4; nf++) {
                int c = wn + nf * 8 + t * 2;
                float2 pv = *(const float2*)(Pr + c);
                float2 qv = *(const float2*)(Qr + c);
                float2 b2 = *(const float2*)(bhh + c);
                int q = sub * 2;
                rf[mf][nf][q]     = sigf(rf[mf][nf][q]     + pv.x + qv.x + b2.x);
                rf[mf][nf][q + 1] = sigf(rf[mf][nf][q + 1] + pv.y + qv.y + b2.y);
            }
        }

    // ---- stage N (weight chunk 2) + blend + store ----
    __syncthreads();
    copy_b_chunk(sm, F0_BHI, Bh_hi + 2 * 2048, tid);
    copy_b_chunk(sm, F0_BLO, Bh_lo + 2 * 2048, tid);
    __syncthreads();
    ZERO_ACC(acc);
    mma_3pass(acc, ah, al, bh_s, bl_s);
#pragma unroll
    for (int mf = 0; mf < 2; mf++)
#pragma unroll
        for (int sub = 0; sub < 2; sub++) {
            int rowl = wm + mf * 16 + g + sub * 8;
            const float* Pr = P + (size_t)src_sm[rowl] * 384 + 256;
            const float* Qr = Q + (size_t)dst_sm[rowl] * 384 + 256;
#pragma unroll
            for (int nf = 0; nf < 4; nf++) {
                int c = wn + nf * 8 + t * 2;
                float2 pv = *(const float2*)(Pr + c);
                float2 qv = *(const float2*)(Qr + c);
                float2 b2 = *(const float2*)(bhh + 256 + c);
                int q = sub * 2;
                float n0 = tanhf(pv.x + qv.x + rf[mf][nf][q]     * (acc[mf][nf][q]     + b2.x));
                float n1 = tanhf(pv.y + qv.y + rf[mf][nf][q + 1] * (acc[mf][nf][q + 1] + b2.y));
                unsigned hh = *(unsigned*)(sm + F0_AHI + rowl * 272 + c * 2);
                unsigned ll = *(unsigned*)(sm + F0_ALO + rowl * 272 + c * 2);
                float hp0 = __uint_as_float(hh << 16) + __uint_as_float(ll << 16);
                float hp1 = __uint_as_float(hh & 0xffff0000u) + __uint_as_float(ll & 0xffff0000u);
                float z0 = zf[mf][nf][q], z1 = zf[mf][nf][q + 1];
                float2 o = make_float2((1.f - z0) * n0 + z0 * hp0,
                                       (1.f - z1) * n1 + z1 * hp1);
                *(float2*)(h0 + (size_t)(m0 + rowl) * 128 + c) = o;
            }
        }
}

// ============================================================================
// Fused GRU layer 1: h1s = GRU(h0, h1s)
// ============================================================================
#define F1_A0HI 0
#define F1_A0LO 17408
#define F1_A1HI 34816
#define F1_A1LO 52224
#define F1_BIHI 69632
#define F1_BILO 104448
#define F1_BHHI 139264
#define F1_BHLO 174080
#define F1_SMEM 208896

__global__ void __launch_bounds__(256) gru1_fused_kernel(
    const float* __restrict__ h0, float* __restrict__ h1s,
    const uint4* __restrict__ Bi_hi, const uint4* __restrict__ Bi_lo,
    const uint4* __restrict__ Bh_hi, const uint4* __restrict__ Bh_lo,
    const float* __restrict__ bih, const float* __restrict__ bhh)
{
    extern __shared__ char sm[];
    const int tid = threadIdx.x, lane = tid & 31, warp = tid >> 5;
    const int m0 = blockIdx.x * 64;
    const int wm = (warp >> 2) * 32, wn = (warp & 3) * 32;
    const int g = lane >> 2, t = lane & 3;

    load_a_split(sm, F1_A0HI, F1_A0LO, h0, m0, tid);
    load_a_split(sm, F1_A1HI, F1_A1LO, h1s, m0, tid);

    const uint32_t sb = smem_u32(sm);
    const uint32_t alo_o = (uint32_t)((wm + (lane & 15)) * 272 + ((lane >> 4) << 4));
    const uint32_t blo_o = (uint32_t)((wn + (lane & 7) + ((lane >> 4) << 3)) * 272
                                      + (((lane >> 3) & 1) << 4));
    const uint32_t a0h = sb + F1_A0HI + alo_o, a0l = sb + F1_A0LO + alo_o;
    const uint32_t a1h = sb + F1_A1HI + alo_o, a1l = sb + F1_A1LO + alo_o;
    const uint32_t bi_h = sb + F1_BIHI + blo_o, bi_l = sb + F1_BILO + blo_o;
    const uint32_t bh_h = sb + F1_BHHI + blo_o, bh_l = sb + F1_BHLO + blo_o;

    float zf[2][4][4], rf[2][4][4], acc[2][4][4];

    // ---- stage Z (chunk 1) ----
    __syncthreads();
    copy_b_chunk(sm, F1_BIHI, Bi_hi + 2048, tid);
    copy_b_chunk(sm, F1_BILO, Bi_lo + 2048, tid);
    copy_b_chunk(sm, F1_BHHI, Bh_hi + 2048, tid);
    copy_b_chunk(sm, F1_BHLO, Bh_lo + 2048, tid);
    __syncthreads();
    ZERO_ACC(zf);
    mma_3pass(zf, a0h, a0l, bi_h, bi_l);
    mma_3pass(zf, a1h, a1l, bh_h, bh_l);
#pragma unroll
    for (int nf = 0; nf < 4; nf++) {
        int c = wn + nf * 8 + t * 2;
        float2 bi2 = *(const float2*)(bih + 128 + c);
        float2 bh2 = *(const float2*)(bhh + 128 + c);
        float bx = bi2.x + bh2.x, by = bi2.y + bh2.y;
#pragma unroll
        for (int mf = 0; mf < 2; mf++) {
            zf[mf][nf][0] = sigf(zf[mf][nf][0] + bx);
            zf[mf][nf][1] = sigf(zf[mf][nf][1] + by);
            zf[mf][nf][2] = sigf(zf[mf][nf][2] + bx);
            zf[mf][nf][3] = sigf(zf[mf][nf][3] + by);
        }
    }

    // ---- stage R (chunk 0) ----
    __syncthreads();
    copy_b_chunk(sm, F1_BIHI, Bi_hi, tid);
    copy_b_chunk(sm, F1_BILO, Bi_lo, tid);
    copy_b_chunk(sm, F1_BHHI, Bh_hi, tid);
    copy_b_chunk(sm, F1_BHLO, Bh_lo, tid);
    __syncthreads();
    ZERO_ACC(rf);
    mma_3pass(rf, a0h, a0l, bi_h, bi_l);
    mma_3pass(rf, a1h, a1l, bh_h, bh_l);
#pragma unroll
    for (int nf = 0; nf < 4; nf++) {
        int c = wn + nf * 8 + t * 2;
        float2 bi2 = *(const float2*)(bih + c);
        float2 bh2 = *(const float2*)(bhh + c);
        float bx = bi2.x + bh2.x, by = bi2.y + bh2.y;
#pragma unroll
        for (int mf = 0; mf < 2; mf++) {
            rf[mf][nf][0] = sigf(rf[mf][nf][0] + bx);
            rf[mf][nf][1] = sigf(rf[mf][nf][1] + by);
            rf[mf][nf][2] = sigf(rf[mf][nf][2] + bx);
            rf[mf][nf][3] = sigf(rf[mf][nf][3] + by);
        }
    }

    // ---- stage N (chunk 2): hn first, transform by r, then accumulate inn ----
    __syncthreads();
    copy_b_chunk(sm, F1_BIHI, Bi_hi + 2 * 2048, tid);
    copy_b_chunk(sm, F1_BILO, Bi_lo + 2 * 2048, tid);
    copy_b_chunk(sm, F1_BHHI, Bh_hi + 2 * 2048, tid);
    copy_b_chunk(sm, F1_BHLO, Bh_lo + 2 * 2048, tid);
    __syncthreads();
    ZERO_ACC(acc);
    mma_3pass(acc, a1h, a1l, bh_h, bh_l);      // hn (no bias yet)
#pragma unroll
    for (int nf = 0; nf < 4; nf++) {
        int c = wn + nf * 8 + t * 2;
        float2 b2 = *(const float2*)(bhh + 256 + c);
#pragma unroll
        for (int mf = 0; mf < 2; mf++) {
            acc[mf][nf][0] = rf[mf][nf][0] * (acc[mf][nf][0] + b2.x);
            acc[mf][nf][1] = rf[mf][nf][1] * (acc[mf][nf][1] + b2.y);
            acc[mf][nf][2] = rf[mf][nf][2] * (acc[mf][nf][2] + b2.x);
            acc[mf][nf][3] = rf[mf][nf][3] * (acc[mf][nf][3] + b2.y);
        }
    }
    mma_3pass(acc, a0h, a0l, bi_h, bi_l);      // += inn

    // ---- epilogue: n = tanh(acc + bih_n); h = (1-z)*n + z*hprev ----
#pragma unroll
    for (int nf = 0; nf < 4; nf++) {
        int c = wn + nf * 8 + t * 2;
        float2 bi2 = *(const float2*)(bih + 256 + c);
#pragma unroll
        for (int mf = 0; mf < 2; mf++)
#pragma unroll
            for (int sub = 0; sub < 2; sub++) {
                int rowl = wm + mf * 16 + g + sub * 8;
                int q = sub * 2;
                float n0 = tanhf(acc[mf][nf][q]     + bi2.x);
                float n1 = tanhf(acc[mf][nf][q + 1] + bi2.y);
                unsigned hh = *(unsigned*)(sm + F1_A1HI + rowl * 272 + c * 2);
                unsigned ll = *(unsigned*)(sm + F1_A1LO + rowl * 272 + c * 2);
                float hp0 = __uint_as_float(hh << 16) + __uint_as_float(ll << 16);
                float hp1 = __uint_as_float(hh & 0xffff0000u) + __uint_as_float(ll & 0xffff0000u);
                float z0 = zf[mf][nf][q], z1 = zf[mf][nf][q + 1];
                float2 o = make_float2((1.f - z0) * n0 + z0 * hp0,
                                       (1.f - z1) * n1 + z1 * hp1);
                *(float2*)(h1s + (size_t)(m0 + rowl) * 128 + c) = o;
            }
    }
}

// ---------------- scalar FFMA2 GEMM (small GEMMs): C = A * B (+bias) ------------
template <bool B_NK, bool RELU>
__global__ void __launch_bounds__(256) sgemm_kernel(
    const float* __restrict__ A, const float* __restrict__ B,
    const float* __restrict__ bias, float* __restrict__ C,
    int M, int K, int ldb, int ldc)
{
    __shared__ float As[16][128];
    __shared__ float Bs[16][64];
    const int tid = threadIdx.x;
    const int m0 = blockIdx.x * 128;
    const int n0 = blockIdx.y * 64;
    const int tx = tid & 15;
    const int ty = tid >> 4;

    ull acc[4][4];
#pragma unroll
    for (int i = 0; i < 4; i++)
#pragma unroll
        for (int j = 0; j < 4; j++) acc[i][j] = 0ULL;

    const int ar = tid >> 2;
    const int ac = (tid & 3) << 2;
    const int nIter = K >> 4;

    for (int it = 0; it < nIter; ++it) {
        const int k0 = it << 4;
#pragma unroll
        for (int half = 0; half < 2; ++half) {
            int row = ar + half * 64;
            float4 v = make_float4(0.f, 0.f, 0.f, 0.f);
            if (m0 + row < M)
                v = *reinterpret_cast<const float4*>(A + (size_t)(m0 + row) * K + k0 + ac);
            As[ac + 0][row] = v.x; As[ac + 1][row] = v.y;
            As[ac + 2][row] = v.z; As[ac + 3][row] = v.w;
        }
        if (B_NK) {
            int n = tid >> 2;
            float4 v = *reinterpret_cast<const float4*>(B + (size_t)(n0 + n) * ldb + k0 + ac);
            Bs[ac + 0][n] = v.x; Bs[ac + 1][n] = v.y;
            Bs[ac + 2][n] = v.z; Bs[ac + 3][n] = v.w;
        } else {
            int kk = tid >> 4;
            int nn = (tid & 15) << 2;
            *reinterpret_cast<float4*>(&Bs[kk][nn]) =
                *reinterpret_cast<const float4*>(B + (size_t)(k0 + kk) * ldb + n0 + nn);
        }
        __syncthreads();
#pragma unroll
        for (int kk = 0; kk < 16; ++kk) {
            ulonglong2 aA = *reinterpret_cast<const ulonglong2*>(&As[kk][ty * 8]);
            ulonglong2 aB = *reinterpret_cast<const ulonglong2*>(&As[kk][ty * 8 + 4]);
            float4 b = *reinterpret_cast<const float4*>(&Bs[kk][tx * 4]);
            ull am0 = aA.x, am1 = aA.y, am2 = aB.x, am3 = aB.y;
            ull bb0 = dup2(b.x), bb1 = dup2(b.y), bb2 = dup2(b.z), bb3 = dup2(b.w);
            acc[0][0] = ffma2(am0, bb0, acc[0][0]); acc[0][1] = ffma2(am0, bb1, acc[0][1]);
            acc[0][2] = ffma2(am0, bb2, acc[0][2]); acc[0][3] = ffma2(am0, bb3, acc[0][3]);
            acc[1][0] = ffma2(am1, bb0, acc[1][0]); acc[1][1] = ffma2(am1, bb1, acc[1][1]);
            acc[1][2] = ffma2(am1, bb2, acc[1][2]); acc[1][3] = ffma2(am1, bb3, acc[1][3]);
            acc[2][0] = ffma2(am2, bb0, acc[2][0]); acc[2][1] = ffma2(am2, bb1, acc[2][1]);
            acc[2][2] = ffma2(am2, bb2, acc[2][2]); acc[2][3] = ffma2(am2, bb3, acc[2][3]);
            acc[3][0] = ffma2(am3, bb0, acc[3][0]); acc[3][1] = ffma2(am3, bb1, acc[3][1]);
            acc[3][2] = ffma2(am3, bb2, acc[3][2]); acc[3][3] = ffma2(am3, bb3, acc[3][3]);
        }
        __syncthreads();
    }

    float4 bv = make_float4(0.f, 0.f, 0.f, 0.f);
    if (bias) bv = *reinterpret_cast<const float4*>(bias + n0 + tx * 4);
#pragma unroll
    for (int i = 0; i < 4; i++) {
        float lo[4], hi[4];
#pragma unroll
        for (int j = 0; j < 4; j++) {
            lo[j] = __uint_as_float((unsigned)(acc[i][j] & 0xffffffffULL));
            hi[j] = __uint_as_float((unsigned)(acc[i][j] >> 32));
        }
        float4 ce = make_float4(lo[0] + bv.x, lo[1] + bv.y, lo[2] + bv.z, lo[3] + bv.w);
        float4 co = make_float4(hi[0] + bv.x, hi[1] + bv.y, hi[2] + bv.z, hi[3] + bv.w);
        if (RELU) {
            ce.x = fmaxf(ce.x, 0.f); ce.y = fmaxf(ce.y, 0.f);
            ce.z = fmaxf(ce.z, 0.f); ce.w = fmaxf(ce.w, 0.f);
            co.x = fmaxf(co.x, 0.f); co.y = fmaxf(co.y, 0.f);
            co.z = fmaxf(co.z, 0.f); co.w = fmaxf(co.w, 0.f);
        }
        int m = m0 + ty * 8 + i * 2;
        if (m < M)
            *reinterpret_cast<float4*>(C + (size_t)m * ldc + n0 + tx * 4) = ce;
        if (m + 1 < M)
            *reinterpret_cast<float4*>(C + (size_t)(m + 1) * ldc + n0 + tx * 4) = co;
    }
}

// ---------------- GAT attention logits ------------
__global__ void alpha4_kernel(const float* __restrict__ h, const float* __restrict__ av,
                              const float* __restrict__ dv, float* __restrict__ als,
                              float* __restrict__ ald)
{
    int idx = blockIdx.x * blockDim.x + threadIdx.x;
    if (idx >= NN * 4) return;
    int i = idx >> 2, hh = idx & 3;
    const float* hp = h + (size_t)i * 256 + hh * 64;
    const float* ap = av + hh * 64;
    const float* dp = dv + hh * 64;
    float ss = 0.f, sd = 0.f;
#pragma unroll
    for (int c = 0; c < 64; c++) { float v = hp[c]; ss += v * ap[c]; sd += v * dp[c]; }
    als[idx] = ss; ald[idx] = sd;
}

__global__ void alpha1_kernel(const float* __restrict__ h, const float* __restrict__ av,
                              const float* __restrict__ dv, float* __restrict__ als,
                              float* __restrict__ ald)
{
    int i = blockIdx.x * blockDim.x + threadIdx.x;
    if (i >= NN) return;
    const float* hp = h + (size_t)i * 64;
    float ss = 0.f, sd = 0.f;
#pragma unroll
    for (int c = 0; c < 64; c++) { float v = hp[c]; ss += v * av[c]; sd += v * dv[c]; }
    als[i] = ss; ald[i] = sd;
}

// ---------------- decoder stage 2 ------------
__global__ void decoder2_kernel(const float* __restrict__ d1, const float* __restrict__ Wd2,
                                const float* __restrict__ bd2, float* __restrict__ out)
{
    int e = blockIdx.x * blockDim.x + threadIdx.x;
    if (e >= EE) return;
    const float* r = d1 + (size_t)e * 64;
    float s = 0.f;
#pragma unroll
    for (int c = 0; c < 64; c++) s += r[c] * Wd2[c];
    out[e] = s + bd2[0];
}

// ---------------- host orchestration ------------
static inline dim3 ggrid(int M, int Ntot) { return dim3((M + 127) / 128, Ntot / 64); }
static inline int gb(int n) { return (n + 255) / 256; }

extern "C" void kernel_launch(void* const* d_in, const int* in_sizes, int n_in,
                              void* d_out, int out_size)
{
    (void)in_sizes; (void)n_in; (void)out_size;
    const float* x_seq  = (const float*)d_in[0];
    const int*   ei     = (const int*)d_in[1];
    const float* W1     = (const float*)d_in[2];
    const float* a_src1 = (const float*)d_in[3];
    const float* a_dst1 = (const float*)d_in[4];
    const float* b1     = (const float*)d_in[5];
    const float* W2     = (const float*)d_in[6];
    const float* a_src2 = (const float*)d_in[7];
    const float* a_dst2 = (const float*)d_in[8];
    const float* b2     = (const float*)d_in[9];
    const float* Wih0   = (const float*)d_in[10];
    const float* Whh0   = (const float*)d_in[11];
    const float* bih0   = (const float*)d_in[12];
    const float* bhh0   = (const float*)d_in[13];
    const float* Wih1   = (const float*)d_in[14];
    const float* Whh1   = (const float*)d_in[15];
    const float* bih1   = (const float*)d_in[16];
    const float* bhh1   = (const float*)d_in[17];
    const float* Wd1    = (const float*)d_in[18];
    const float* bd1    = (const float*)d_in[19];
    const float* Wd2    = (const float*)d_in[20];
    const float* bd2    = (const float*)d_in[21];
    float* out = (float*)d_out;

    float *p_h1lin, *p_als1, *p_ald1, *p_out1;
    float *p_h2lin, *p_als2, *p_ald2, *p_h2;
    float *p_P, *p_Q, *p_h0, *p_h1s, *p_dec1;
    int *p_cnt, *p_ptr, *p_woff, *p_csr;
    __nv_bfloat16* p_wimg;
    cudaGetSymbolAddress((void**)&p_h1lin, g_h1lin);
    cudaGetSymbolAddress((void**)&p_als1, g_als1);
    cudaGetSymbolAddress((void**)&p_ald1, g_ald1);
    cudaGetSymbolAddress((void**)&p_out1, g_out1);
    cudaGetSymbolAddress((void**)&p_h2lin, g_h2lin);
    cudaGetSymbolAddress((void**)&p_als2, g_als2);
    cudaGetSymbolAddress((void**)&p_ald2, g_ald2);
    cudaGetSymbolAddress((void**)&p_h2, g_h2);
    cudaGetSymbolAddress((void**)&p_P, g_P);
    cudaGetSymbolAddress((void**)&p_Q, g_Q);
    cudaGetSymbolAddress((void**)&p_h0, g_h0);
    cudaGetSymbolAddress((void**)&p_h1s, g_h1s);
    cudaGetSymbolAddress((void**)&p_dec1, g_dec1);
    cudaGetSymbolAddress((void**)&p_cnt, g_cnt);
    cudaGetSymbolAddress((void**)&p_ptr, g_ptr);
    cudaGetSymbolAddress((void**)&p_woff, g_woff);
    cudaGetSymbolAddress((void**)&p_csr, g_csr_src);
    cudaGetSymbolAddress((void**)&p_wimg, g_wimg);

    cudaFuncSetAttribute(gru0_fused_kernel, cudaFuncAttributeMaxDynamicSharedMemorySize, F0_SMEM);
    cudaFuncSetAttribute(gru1_fused_kernel, cudaFuncAttributeMaxDynamicSharedMemorySize, F1_SMEM);

    const __nv_bfloat16* whh0h = p_wimg + 0 * W_ELEMS;
    const __nv_bfloat16* whh0l = p_wimg + 1 * W_ELEMS;
    const __nv_bfloat16* wih1h = p_wimg + 2 * W_ELEMS;
    const __nv_bfloat16* wih1l = p_wimg + 3 * W_ELEMS;
    const __nv_bfloat16* whh1h = p_wimg + 4 * W_ELEMS;
    const __nv_bfloat16* whh1l = p_wimg + 5 * W_ELEMS;

    // reset recurrent state every call
    cudaMemsetAsync(p_h0, 0, (size_t)EE * 128 * sizeof(float), 0);
    cudaMemsetAsync(p_h1s, 0, (size_t)EE * 128 * sizeof(float), 0);

    // weight conversion to bf16 hi/lo images
    conv_w_kernel<<<gb(W_ELEMS), 256>>>(Whh0, (__nv_bfloat16*)whh0h, (__nv_bfloat16*)whh0l);
    conv_w_kernel<<<gb(W_ELEMS), 256>>>(Wih1, (__nv_bfloat16*)wih1h, (__nv_bfloat16*)wih1l);
    conv_w_kernel<<<gb(W_ELEMS), 256>>>(Whh1, (__nv_bfloat16*)whh1h, (__nv_bfloat16*)whh1l);

    // ---- build dst-grouped CSR once per call (graph static across timesteps) ----
    cudaMemsetAsync(p_cnt, 0, NN * sizeof(int), 0);
    csr_count_kernel<<<gb(EE), 256>>>(ei, p_cnt);
    csr_scan_kernel<<<1, 1024>>>(p_cnt, p_ptr, p_woff);
    csr_scatter_kernel<<<gb(EE), 256>>>(ei, p_woff, p_csr);

    const int agg_grid = (NN + 7) / 8;

    for (int t = 0; t < T_STEPS; ++t) {
        const float* x_t = x_seq + (size_t)t * NN * 32;

        // ---- GAT layer 1 (CSR gather, no atomics) ----
        sgemm_kernel<false, false><<<ggrid(NN, 256), 256>>>(x_t, W1, nullptr, p_h1lin,
                                                            NN, 32, 256, 256);
        alpha4_kernel<<<gb(NN * 4), 256>>>(p_h1lin, a_src1, a_dst1, p_als1, p_ald1);
        gat1_agg_kernel<<<agg_grid, 256>>>(p_ptr, p_csr, p_h1lin, p_als1, p_ald1, b1, p_out1);

        // ---- GAT layer 2 ----
        sgemm_kernel<false, false><<<ggrid(NN, 64), 256>>>(p_out1, W2, nullptr, p_h2lin,
                                                           NN, 256, 64, 64);
        alpha1_kernel<<<gb(NN), 256>>>(p_h2lin, a_src2, a_dst2, p_als2, p_ald2);
        gat2_agg_kernel<<<agg_grid, 256>>>(p_ptr, p_csr, p_h2lin, p_als2, p_ald2, b2, p_h2);

        // ---- GRU layer 0: node-level P/Q, then fused GEMM+gate ----
        sgemm_kernel<true, false><<<ggrid(NN, 384), 256>>>(p_h2, Wih0, bih0, p_P,
                                                           NN, 64, 128, 384);
        sgemm_kernel<true, false><<<ggrid(NN, 384), 256>>>(p_h2, Wih0 + 64, nullptr, p_Q,
                                                           NN, 64, 128, 384);
        gru0_fused_kernel<<<EE / 64, 256, F0_SMEM>>>(ei, p_P, p_Q, p_h0,
            (const uint4*)whh0h, (const uint4*)whh0l, bhh0);

        // ---- GRU layer 1: fully fused ----
        gru1_fused_kernel<<<EE / 64, 256, F1_SMEM>>>(p_h0, p_h1s,
            (const uint4*)wih1h, (const uint4*)wih1l,
            (const uint4*)whh1h, (const uint4*)whh1l, bih1, bhh1);
    }

    // ---- decoder ----
    sgemm_kernel<false, true><<<ggrid(EE, 64), 256>>>(p_h1s, Wd1, bd1, p_dec1,
                                                      EE, 128, 64, 64);
    decoder2_kernel<<<gb(EE), 256>>>(p_dec1, Wd2, bd2, out);
}

// round 15
// speedup vs baseline: 2.8536x; 1.3334x over previous
#include <cuda_runtime.h>
#include <cuda_bf16.h>
#include <cstdint>

typedef unsigned long long ull;

#define T_STEPS 8
#define NN 20000
#define EE 320000
#define ET (EE + NN)

// ---------------- scratch (static device globals; no allocation at run time) ------------
__device__ __align__(16) float g_h1lin[NN * 256];
__device__ __align__(16) float g_als1[NN * 4];
__device__ __align__(16) float g_ald1[NN * 4];
__device__ __align__(16) float g_out1[NN * 256];
__device__ __align__(16) float g_h2lin[NN * 64];
__device__ __align__(16) float g_als2[NN];
__device__ __align__(16) float g_ald2[NN];
__device__ __align__(16) float g_h2[NN * 64];
__device__ __align__(16) float g_P[NN * 384];
__device__ __align__(16) float g_Q[NN * 384];
__device__ __align__(16) float g_h0[(size_t)EE * 128];
__device__ __align__(16) float g_h1s[(size_t)EE * 128];
__device__ __align__(16) float g_dec1[(size_t)EE * 64];

// CSR (dst-grouped incoming edges), rebuilt once per call
__device__ int g_cnt[NN];
__device__ int g_ptr[NN + 1];
__device__ int g_woff[NN];
__device__ int g_csr_src[EE];

// bf16 weight images [384][128] row-major:
// [0]=Whh0 hi, [1]=Whh0 lo, [2]=Wih1 hi, [3]=Wih1 lo, [4]=Whh1 hi, [5]=Whh1 lo
#define W_ELEMS (384 * 128)
__device__ __align__(16) __nv_bfloat16 g_wimg[6][W_ELEMS];

// ---------------- packed fp32x2 helpers (sm_103a FFMA2) ------------
__device__ __forceinline__ ull dup2(float x) {
    ull r;
    unsigned u = __float_as_uint(x);
    asm("mov.b64 %0, {%1, %1};" : "=l"(r) : "r"(u));
    return r;
}
__device__ __forceinline__ ull ffma2(ull a, ull b, ull c) {
    ull d;
    asm("fma.rn.f32x2 %0, %1, %2, %3;" : "=l"(d) : "l"(a), "l"(b), "l"(c));
    return d;
}

__device__ __forceinline__ uint32_t smem_u32(const void* p) {
    uint32_t a;
    asm("{ .reg .u64 t; cvta.to.shared.u64 t, %1; cvt.u32.u64 %0, t; }" : "=r"(a) : "l"(p));
    return a;
}
// HW tanh (sm_75+): 1 MUFU op, rel err ~2^-10.9 — well inside the 1e-3 gate
__device__ __forceinline__ float tanh_fast(float x) {
    float y;
    asm("tanh.approx.f32 %0, %1;" : "=f"(y) : "f"(x));
    return y;
}
__device__ __forceinline__ float sigf(float x) {
    return fmaf(tanh_fast(0.5f * x), 0.5f, 0.5f);
}
__device__ __forceinline__ float eluf(float x) { return x > 0.f ? x : expm1f(x); }
__device__ __forceinline__ float lrelu(float x) { return x >= 0.f ? x : 0.2f * x; }

// ---------------- mma.sync helpers (family-portable: sm_80+) ------------
__device__ __forceinline__ void ldsm4(uint32_t* r, uint32_t addr) {
    asm volatile("ldmatrix.sync.aligned.m8n8.x4.shared.b16 {%0,%1,%2,%3}, [%4];"
        : "=r"(r[0]), "=r"(r[1]), "=r"(r[2]), "=r"(r[3]) : "r"(addr));
}
__device__ __forceinline__ void mma_bf16(float* c, const uint32_t* a, uint32_t b0, uint32_t b1) {
    asm volatile("mma.sync.aligned.m16n8k16.row.col.f32.bf16.bf16.f32 "
        "{%0,%1,%2,%3}, {%4,%5,%6,%7}, {%8,%9}, {%0,%1,%2,%3};"
        : "+f"(c[0]), "+f"(c[1]), "+f"(c[2]), "+f"(c[3])
        : "r"(a[0]), "r"(a[1]), "r"(a[2]), "r"(a[3]), "r"(b0), "r"(b1));
}

// Shared building blocks: A tiles 64 rows x 128 k, SMEM row stride 272 B (136 bf16, pad)
__device__ __forceinline__ void copy_b_chunk(char* sm, int off, const uint4* __restrict__ src,
                                             int tid)
{
#pragma unroll
    for (int rep = 0; rep < 8; rep++) {
        int i = rep * 256 + tid;
        int n = i >> 4, seg = i & 15;
        *(uint4*)(sm + off + n * 272 + seg * 16) = src[i];
    }
}

__device__ __forceinline__ void load_a_split(char* sm, int offHi, int offLo,
                                             const float* __restrict__ A, int m0, int tid)
{
    const float4* Ap = (const float4*)(A + (size_t)m0 * 128);
#pragma unroll
    for (int rep = 0; rep < 8; rep++) {
        int flat = rep * 256 + tid;
        float4 v = Ap[flat];
        int m = flat >> 5, k = (flat & 31) << 2;
        __nv_bfloat162 h01 = __float22bfloat162_rn(make_float2(v.x, v.y));
        __nv_bfloat162 h23 = __float22bfloat162_rn(make_float2(v.z, v.w));
        float2 f01 = __bfloat1622float2(h01);
        float2 f23 = __bfloat1622float2(h23);
        __nv_bfloat162 l01 = __float22bfloat162_rn(make_float2(v.x - f01.x, v.y - f01.y));
        __nv_bfloat162 l23 = __float22bfloat162_rn(make_float2(v.z - f23.x, v.w - f23.y));
        int doff = m * 272 + k * 2;
        *(uint2*)(sm + offHi + doff) = make_uint2(*(unsigned*)&h01, *(unsigned*)&h23);
        *(uint2*)(sm + offLo + doff) = make_uint2(*(unsigned*)&l01, *(unsigned*)&l23);
    }
}

// N-pass bf16 split MMA over K=128 (8 ksteps).
// pass0: Ahi*Bhi; pass1: +Alo*Bhi; pass2: +Ahi*Blo.
// NPASS=2 -> weights effectively bf16 (z/r gates); NPASS=3 -> full split (n gate).
template <int NPASS>
__device__ __forceinline__ void mma_pass(float acc[2][4][4],
    uint32_t aHi, uint32_t aLo, uint32_t bHi, uint32_t bLo)
{
#pragma unroll 1
    for (int pass = 0; pass < NPASS; pass++) {
        const uint32_t aa = (pass == 1) ? aLo : aHi;
        const uint32_t bb = (pass == 2) ? bLo : bHi;
#pragma unroll
        for (int ks = 0; ks < 8; ks++) {
            uint32_t af[2][4], bf[2][4];
            ldsm4(af[0], aa + ks * 32);
            ldsm4(af[1], aa + 4352 + ks * 32);
            ldsm4(bf[0], bb + ks * 32);
            ldsm4(bf[1], bb + 4352 + ks * 32);
#pragma unroll
            for (int mf = 0; mf < 2; mf++)
#pragma unroll
                for (int nf = 0; nf < 4; nf++)
                    mma_bf16(acc[mf][nf], af[mf],
                             bf[nf >> 1][(nf & 1) * 2], bf[nf >> 1][(nf & 1) * 2 + 1]);
        }
    }
}

#define ZERO_ACC(a) do { \
_Pragma("unroll") for (int _i = 0; _i < 2; _i++) \
_Pragma("unroll") for (int _j = 0; _j < 4; _j++) \
_Pragma("unroll") for (int _q = 0; _q < 4; _q++) (a)[_i][_j][_q] = 0.f; } while (0)

// -------- one-time weight conversion: fp32 [384,128] -> bf16 hi/lo images --------
__global__ void conv_w_kernel(const float* __restrict__ W, __nv_bfloat16* __restrict__ hi,
                              __nv_bfloat16* __restrict__ lo)
{
    int idx = blockIdx.x * blockDim.x + threadIdx.x;
    if (idx >= W_ELEMS) return;
    float v = W[idx];
    __nv_bfloat16 h = __float2bfloat16_rn(v);
    hi[idx] = h;
    lo[idx] = __float2bfloat16_rn(v - __bfloat162float(h));
}

// ============================ CSR construction (once per call) ============================
__global__ void csr_count_kernel(const int* __restrict__ ei, int* __restrict__ cnt)
{
    int e = blockIdx.x * blockDim.x + threadIdx.x;
    if (e >= EE) return;
    atomicAdd(&cnt[ei[EE + e]], 1);
}

__global__ void __launch_bounds__(1024) csr_scan_kernel(
    const int* __restrict__ cnt, int* __restrict__ ptr, int* __restrict__ woff)
{
    __shared__ int part[1024];
    const int t = threadIdx.x;
    const int base = t * 20;                    // 1024*20 = 20480 >= NN
    int s = 0;
#pragma unroll
    for (int i = 0; i < 20; i++) {
        int idx = base + i;
        if (idx < NN) s += cnt[idx];
    }
    part[t] = s;
    __syncthreads();
    for (int off = 1; off < 1024; off <<= 1) {
        int v = (t >= off) ? part[t - off] : 0;
        __syncthreads();
        part[t] += v;
        __syncthreads();
    }
    int run = (t > 0) ? part[t - 1] : 0;
#pragma unroll
    for (int i = 0; i < 20; i++) {
        int idx = base + i;
        if (idx < NN) { ptr[idx] = run; woff[idx] = run; run += cnt[idx]; }
    }
    if (t == 0) ptr[NN] = part[1023];
}

__global__ void csr_scatter_kernel(const int* __restrict__ ei, int* __restrict__ woff,
                                   int* __restrict__ csr_src)
{
    int e = blockIdx.x * blockDim.x + threadIdx.x;
    if (e >= EE) return;
    int d = ei[EE + e];
    int pos = atomicAdd(&woff[d], 1);
    csr_src[pos] = ei[e];
}

// ================== GAT aggregation: warp-per-node CSR gather (no atomics) ==============
__global__ void __launch_bounds__(256) gat1_agg_kernel(
    const int* __restrict__ ptr, const int* __restrict__ csr_src,
    const float* __restrict__ hlin, const float* __restrict__ als,
    const float* __restrict__ ald, const float* __restrict__ b1,
    float* __restrict__ out1)
{
    const int node = blockIdx.x * 8 + (threadIdx.x >> 5);
    if (node >= NN) return;
    const int lane = threadIdx.x & 31;
    const int h = lane >> 3;

    const float aldv = ald[node * 4 + h];
    float den = __expf(lrelu(als[node * 4 + h] + aldv));   // self loop
    const float4* hp = (const float4*)(hlin + (size_t)node * 256) + lane * 2;
    float4 s0 = hp[0], s1 = hp[1];
    float a0 = den * s0.x, a1 = den * s0.y, a2 = den * s0.z, a3 = den * s0.w;
    float a4 = den * s1.x, a5 = den * s1.y, a6 = den * s1.z, a7 = den * s1.w;

    const int end = ptr[node + 1];
    for (int j = ptr[node]; j < end; j++) {
        int s = csr_src[j];                               // warp-uniform
        float w = __expf(lrelu(als[s * 4 + h] + aldv));
        den += w;
        const float4* sp = (const float4*)(hlin + (size_t)s * 256) + lane * 2;
        float4 u0 = sp[0], u1 = sp[1];
        a0 += w * u0.x; a1 += w * u0.y; a2 += w * u0.z; a3 += w * u0.w;
        a4 += w * u1.x; a5 += w * u1.y; a6 += w * u1.z; a7 += w * u1.w;
    }
    const float inv = __fdividef(1.f, den + 1e-16f);
    const float4* bp = (const float4*)b1 + lane * 2;
    float4 bv0 = bp[0], bv1 = bp[1];
    float4 o0 = make_float4(eluf(a0 * inv + bv0.x), eluf(a1 * inv + bv0.y),
                            eluf(a2 * inv + bv0.z), eluf(a3 * inv + bv0.w));
    float4 o1 = make_float4(eluf(a4 * inv + bv1.x), eluf(a5 * inv + bv1.y),
                            eluf(a6 * inv + bv1.z), eluf(a7 * inv + bv1.w));
    float4* op = (float4*)(out1 + (size_t)node * 256) + lane * 2;
    op[0] = o0; op[1] = o1;
}

__global__ void __launch_bounds__(256) gat2_agg_kernel(
    const int* __restrict__ ptr, const int* __restrict__ csr_src,
    const float* __restrict__ hlin, const float* __restrict__ als,
    const float* __restrict__ ald, const float* __restrict__ b2,
    float* __restrict__ h2)
{
    const int node = blockIdx.x * 8 + (threadIdx.x >> 5);
    if (node >= NN) return;
    const int lane = threadIdx.x & 31;

    const float aldv = ald[node];
    float den = __expf(lrelu(als[node] + aldv));          // self loop
    float2 sv = *(const float2*)(hlin + (size_t)node * 64 + lane * 2);
    float a0 = den * sv.x, a1 = den * sv.y;

    const int end = ptr[node + 1];
    for (int j = ptr[node]; j < end; j++) {
        int s = csr_src[j];
        float w = __expf(lrelu(als[s] + aldv));
        den += w;
        float2 u = *(const float2*)(hlin + (size_t)s * 64 + lane * 2);
        a0 += w * u.x; a1 += w * u.y;
    }
    const float inv = __fdividef(1.f, den + 1e-16f);
    float2 bv = *(const float2*)(b2 + lane * 2);
    *(float2*)(h2 + (size_t)node * 64 + lane * 2) =
        make_float2(a0 * inv + bv.x, a1 * inv + bv.y);
}

// ============================================================================
// Fused GRU layer 0: h0 = GRU(P[src]+Q[dst] as gi, h0)
// ============================================================================
#define F0_AHI 0
#define F0_ALO 17408
#define F0_BHI 34816
#define F0_BLO 69632
#define F0_SRC 104448
#define F0_DST 104704
#define F0_SMEM 104960

__global__ void __launch_bounds__(256) gru0_fused_kernel(
    const int* __restrict__ ei, const float* __restrict__ P, const float* __restrict__ Q,
    float* __restrict__ h0, const uint4* __restrict__ Bh_hi, const uint4* __restrict__ Bh_lo,
    const float* __restrict__ bhh)
{
    extern __shared__ char sm[];
    const int tid = threadIdx.x, lane = tid & 31, warp = tid >> 5;
    const int m0 = blockIdx.x * 64;
    const int wm = (warp >> 2) * 32, wn = (warp & 3) * 32;
    const int g = lane >> 2, t = lane & 3;

    load_a_split(sm, F0_AHI, F0_ALO, h0, m0, tid);
    if (tid < 64) {
        ((int*)(sm + F0_SRC))[tid] = ei[m0 + tid];
        ((int*)(sm + F0_DST))[tid] = ei[EE + m0 + tid];
    }
    const int* src_sm = (const int*)(sm + F0_SRC);
    const int* dst_sm = (const int*)(sm + F0_DST);

    const uint32_t sb = smem_u32(sm);
    const uint32_t alo_o = (uint32_t)((wm + (lane & 15)) * 272 + ((lane >> 4) << 4));
    const uint32_t blo_o = (uint32_t)((wn + (lane & 7) + ((lane >> 4) << 3)) * 272
                                      + (((lane >> 3) & 1) << 4));
    const uint32_t ah = sb + F0_AHI + alo_o, al = sb + F0_ALO + alo_o;
    const uint32_t bh_s = sb + F0_BHI + blo_o, bl_s = sb + F0_BLO + blo_o;

    float zf[2][4][4], rf[2][4][4], acc[2][4][4];

    // ---- stage Z (weight chunk 1): 2-pass, B-hi only ----
    __syncthreads();
    copy_b_chunk(sm, F0_BHI, Bh_hi + 2048, tid);
    __syncthreads();
    ZERO_ACC(zf);
    mma_pass<2>(zf, ah, al, bh_s, bl_s);
#pragma unroll
    for (int mf = 0; mf < 2; mf++)
#pragma unroll
        for (int sub = 0; sub < 2; sub++) {
            int rowl = wm + mf * 16 + g + sub * 8;
            const float* Pr = P + (size_t)src_sm[rowl] * 384 + 128;
            const float* Qr = Q + (size_t)dst_sm[rowl] * 384 + 128;
#pragma unroll
            for (int nf = 0; nf < 4; nf++) {
                int c = wn + nf * 8 + t * 2;
                float2 pv = *(const float2*)(Pr + c);
                float2 qv = *(const float2*)(Qr + c);
                float2 b2 = *(const float2*)(bhh + 128 + c);
                int q = sub * 2;
                zf[mf][nf][q]     = sigf(zf[mf][nf][q]     + pv.x + qv.x + b2.x);
                zf[mf][nf][q + 1] = sigf(zf[mf][nf][q + 1] + pv.y + qv.y + b2.y);
            }
        }

    // ---- stage R (weight chunk 0): 2-pass, B-hi only ----
    __syncthreads();
    copy_b_chunk(sm, F0_BHI, Bh_hi, tid);
    __syncthreads();
    ZERO_ACC(rf);
    mma_pass<2>(rf, ah, al, bh_s, bl_s);
#pragma unroll
    for (int mf = 0; mf < 2; mf++)
#pragma unroll
        for (int sub = 0; sub < 2; sub++) {
            int rowl = wm + mf * 16 + g + sub * 8;
            const float* Pr = P + (size_t)src_sm[rowl] * 384;
            const float* Qr = Q + (size_t)dst_sm[rowl] * 384;
#pragma unroll
            for (int nf = 0; nf < 4; nf++) {
                int c = wn + nf * 8 + t * 2;
                float2 pv = *(const float2*)(Pr + c);
                float2 qv = *(const float2*)(Qr + c);
                float2 b2 = *(const float2*)(bhh + c);
                int q = sub * 2;
                rf[mf][nf][q]     = sigf(rf[mf][nf][q]     + pv.x + qv.x + b2.x);
                rf[mf][nf][q + 1] = sigf(rf[mf][nf][q + 1] + pv.y + qv.y + b2.y);
            }
        }

    // ---- stage N (weight chunk 2): full 3-pass + blend + store ----
    __syncthreads();
    copy_b_chunk(sm, F0_BHI, Bh_hi + 2 * 2048, tid);
    copy_b_chunk(sm, F0_BLO, Bh_lo + 2 * 2048, tid);
    __syncthreads();
    ZERO_ACC(acc);
    mma_pass<3>(acc, ah, al, bh_s, bl_s);
#pragma unroll
    for (int mf = 0; mf < 2; mf++)
#pragma unroll
        for (int sub = 0; sub < 2; sub++) {
            int rowl = wm + mf * 16 + g + sub * 8;
            const float* Pr = P + (size_t)src_sm[rowl] * 384 + 256;
            const float* Qr = Q + (size_t)dst_sm[rowl] * 384 + 256;
#pragma unroll
            for (int nf = 0; nf < 4; nf++) {
                int c = wn + nf * 8 + t * 2;
                float2 pv = *(const float2*)(Pr + c);
                float2 qv = *(const float2*)(Qr + c);
                float2 b2 = *(const float2*)(bhh + 256 + c);
                int q = sub * 2;
                float n0 = tanh_fast(pv.x + qv.x + rf[mf][nf][q]     * (acc[mf][nf][q]     + b2.x));
                float n1 = tanh_fast(pv.y + qv.y + rf[mf][nf][q + 1] * (acc[mf][nf][q + 1] + b2.y));
                unsigned hh = *(unsigned*)(sm + F0_AHI + rowl * 272 + c * 2);
                unsigned ll = *(unsigned*)(sm + F0_ALO + rowl * 272 + c * 2);
                float hp0 = __uint_as_float(hh << 16) + __uint_as_float(ll << 16);
                float hp1 = __uint_as_float(hh & 0xffff0000u) + __uint_as_float(ll & 0xffff0000u);
                float z0 = zf[mf][nf][q], z1 = zf[mf][nf][q + 1];
                float2 o = make_float2((1.f - z0) * n0 + z0 * hp0,
                                       (1.f - z1) * n1 + z1 * hp1);
                *(float2*)(h0 + (size_t)(m0 + rowl) * 128 + c) = o;
            }
        }
}

// ============================================================================
// Fused GRU layer 1: h1s = GRU(h0, h1s)
// ============================================================================
#define F1_A0HI 0
#define F1_A0LO 17408
#define F1_A1HI 34816
#define F1_A1LO 52224
#define F1_BIHI 69632
#define F1_BILO 104448
#define F1_BHHI 139264
#define F1_BHLO 174080
#define F1_SMEM 208896

__global__ void __launch_bounds__(256) gru1_fused_kernel(
    const float* __restrict__ h0, float* __restrict__ h1s,
    const uint4* __restrict__ Bi_hi, const uint4* __restrict__ Bi_lo,
    const uint4* __restrict__ Bh_hi, const uint4* __restrict__ Bh_lo,
    const float* __restrict__ bih, const float* __restrict__ bhh)
{
    extern __shared__ char sm[];
    const int tid = threadIdx.x, lane = tid & 31, warp = tid >> 5;
    const int m0 = blockIdx.x * 64;
    const int wm = (warp >> 2) * 32, wn = (warp & 3) * 32;
    const int g = lane >> 2, t = lane & 3;

    load_a_split(sm, F1_A0HI, F1_A0LO, h0, m0, tid);
    load_a_split(sm, F1_A1HI, F1_A1LO, h1s, m0, tid);

    const uint32_t sb = smem_u32(sm);
    const uint32_t alo_o = (uint32_t)((wm + (lane & 15)) * 272 + ((lane >> 4) << 4));
    const uint32_t blo_o = (uint32_t)((wn + (lane & 7) + ((lane >> 4) << 3)) * 272
                                      + (((lane >> 3) & 1) << 4));
    const uint32_t a0h = sb + F1_A0HI + alo_o, a0l = sb + F1_A0LO + alo_o;
    const uint32_t a1h = sb + F1_A1HI + alo_o, a1l = sb + F1_A1LO + alo_o;
    const uint32_t bi_h = sb + F1_BIHI + blo_o, bi_l = sb + F1_BILO + blo_o;
    const uint32_t bh_h = sb + F1_BHHI + blo_o, bh_l = sb + F1_BHLO + blo_o;

    float zf[2][4][4], rf[2][4][4], acc[2][4][4];

    // ---- stage Z (chunk 1): 2-pass, B-hi only ----
    __syncthreads();
    copy_b_chunk(sm, F1_BIHI, Bi_hi + 2048, tid);
    copy_b_chunk(sm, F1_BHHI, Bh_hi + 2048, tid);
    __syncthreads();
    ZERO_ACC(zf);
    mma_pass<2>(zf, a0h, a0l, bi_h, bi_l);
    mma_pass<2>(zf, a1h, a1l, bh_h, bh_l);
#pragma unroll
    for (int nf = 0; nf < 4; nf++) {
        int c = wn + nf * 8 + t * 2;
        float2 bi2 = *(const float2*)(bih + 128 + c);
        float2 bh2 = *(const float2*)(bhh + 128 + c);
        float bx = bi2.x + bh2.x, by = bi2.y + bh2.y;
#pragma unroll
        for (int mf = 0; mf < 2; mf++) {
            zf[mf][nf][0] = sigf(zf[mf][nf][0] + bx);
            zf[mf][nf][1] = sigf(zf[mf][nf][1] + by);
            zf[mf][nf][2] = sigf(zf[mf][nf][2] + bx);
            zf[mf][nf][3] = sigf(zf[mf][nf][3] + by);
        }
    }

    // ---- stage R (chunk 0): 2-pass, B-hi only ----
    __syncthreads();
    copy_b_chunk(sm, F1_BIHI, Bi_hi, tid);
    copy_b_chunk(sm, F1_BHHI, Bh_hi, tid);
    __syncthreads();
    ZERO_ACC(rf);
    mma_pass<2>(rf, a0h, a0l, bi_h, bi_l);
    mma_pass<2>(rf, a1h, a1l, bh_h, bh_l);
#pragma unroll
    for (int nf = 0; nf < 4; nf++) {
        int c = wn + nf * 8 + t * 2;
        float2 bi2 = *(const float2*)(bih + c);
        float2 bh2 = *(const float2*)(bhh + c);
        float bx = bi2.x + bh2.x, by = bi2.y + bh2.y;
#pragma unroll
        for (int mf = 0; mf < 2; mf++) {
            rf[mf][nf][0] = sigf(rf[mf][nf][0] + bx);
            rf[mf][nf][1] = sigf(rf[mf][nf][1] + by);
            rf[mf][nf][2] = sigf(rf[mf][nf][2] + bx);
            rf[mf][nf][3] = sigf(rf[mf][nf][3] + by);
        }
    }

    // ---- stage N (chunk 2): full 3-pass; hn first, transform by r, then += inn ----
    __syncthreads();
    copy_b_chunk(sm, F1_BIHI, Bi_hi + 2 * 2048, tid);
    copy_b_chunk(sm, F1_BILO, Bi_lo + 2 * 2048, tid);
    copy_b_chunk(sm, F1_BHHI, Bh_hi + 2 * 2048, tid);
    copy_b_chunk(sm, F1_BHLO, Bh_lo + 2 * 2048, tid);
    __syncthreads();
    ZERO_ACC(acc);
    mma_pass<3>(acc, a1h, a1l, bh_h, bh_l);      // hn (no bias yet)
#pragma unroll
    for (int nf = 0; nf < 4; nf++) {
        int c = wn + nf * 8 + t * 2;
        float2 b2 = *(const float2*)(bhh + 256 + c);
#pragma unroll
        for (int mf = 0; mf < 2; mf++) {
            acc[mf][nf][0] = rf[mf][nf][0] * (acc[mf][nf][0] + b2.x);
            acc[mf][nf][1] = rf[mf][nf][1] * (acc[mf][nf][1] + b2.y);
            acc[mf][nf][2] = rf[mf][nf][2] * (acc[mf][nf][2] + b2.x);
            acc[mf][nf][3] = rf[mf][nf][3] * (acc[mf][nf][3] + b2.y);
        }
    }
    mma_pass<3>(acc, a0h, a0l, bi_h, bi_l);      // += inn

    // ---- epilogue: n = tanh(acc + bih_n); h = (1-z)*n + z*hprev ----
#pragma unroll
    for (int nf = 0; nf < 4; nf++) {
        int c = wn + nf * 8 + t * 2;
        float2 bi2 = *(const float2*)(bih + 256 + c);
#pragma unroll
        for (int mf = 0; mf < 2; mf++)
#pragma unroll
            for (int sub = 0; sub < 2; sub++) {
                int rowl = wm + mf * 16 + g + sub * 8;
                int q = sub * 2;
                float n0 = tanh_fast(acc[mf][nf][q]     + bi2.x);
                float n1 = tanh_fast(acc[mf][nf][q + 1] + bi2.y);
                unsigned hh = *(unsigned*)(sm + F1_A1HI + rowl * 272 + c * 2);
                unsigned ll = *(unsigned*)(sm + F1_A1LO + rowl * 272 + c * 2);
                float hp0 = __uint_as_float(hh << 16) + __uint_as_float(ll << 16);
                float hp1 = __uint_as_float(hh & 0xffff0000u) + __uint_as_float(ll & 0xffff0000u);
                float z0 = zf[mf][nf][q], z1 = zf[mf][nf][q + 1];
                float2 o = make_float2((1.f - z0) * n0 + z0 * hp0,
                                       (1.f - z1) * n1 + z1 * hp1);
                *(float2*)(h1s + (size_t)(m0 + rowl) * 128 + c) = o;
            }
    }
}

// ---------------- scalar FFMA2 GEMM (small GEMMs): C = A * B (+bias) ------------
template <bool B_NK, bool RELU>
__global__ void __launch_bounds__(256) sgemm_kernel(
    const float* __restrict__ A, const float* __restrict__ B,
    const float* __restrict__ bias, float* __restrict__ C,
    int M, int K, int ldb, int ldc)
{
    __shared__ float As[16][128];
    __shared__ float Bs[16][64];
    const int tid = threadIdx.x;
    const int m0 = blockIdx.x * 128;
    const int n0 = blockIdx.y * 64;
    const int tx = tid & 15;
    const int ty = tid >> 4;

    ull acc[4][4];
#pragma unroll
    for (int i = 0; i < 4; i++)
#pragma unroll
        for (int j = 0; j < 4; j++) acc[i][j] = 0ULL;

    const int ar = tid >> 2;
    const int ac = (tid & 3) << 2;
    const int nIter = K >> 4;

    for (int it = 0; it < nIter; ++it) {
        const int k0 = it << 4;
#pragma unroll
        for (int half = 0; half < 2; ++half) {
            int row = ar + half * 64;
            float4 v = make_float4(0.f, 0.f, 0.f, 0.f);
            if (m0 + row < M)
                v = *reinterpret_cast<const float4*>(A + (size_t)(m0 + row) * K + k0 + ac);
            As[ac + 0][row] = v.x; As[ac + 1][row] = v.y;
            As[ac + 2][row] = v.z; As[ac + 3][row] = v.w;
        }
        if (B_NK) {
            int n = tid >> 2;
            float4 v = *reinterpret_cast<const float4*>(B + (size_t)(n0 + n) * ldb + k0 + ac);
            Bs[ac + 0][n] = v.x; Bs[ac + 1][n] = v.y;
            Bs[ac + 2][n] = v.z; Bs[ac + 3][n] = v.w;
        } else {
            int kk = tid >> 4;
            int nn = (tid & 15) << 2;
            *reinterpret_cast<float4*>(&Bs[kk][nn]) =
                *reinterpret_cast<const float4*>(B + (size_t)(k0 + kk) * ldb + n0 + nn);
        }
        __syncthreads();
#pragma unroll
        for (int kk = 0; kk < 16; ++kk) {
            ulonglong2 aA = *reinterpret_cast<const ulonglong2*>(&As[kk][ty * 8]);
            ulonglong2 aB = *reinterpret_cast<const ulonglong2*>(&As[kk][ty * 8 + 4]);
            float4 b = *reinterpret_cast<const float4*>(&Bs[kk][tx * 4]);
            ull am0 = aA.x, am1 = aA.y, am2 = aB.x, am3 = aB.y;
            ull bb0 = dup2(b.x), bb1 = dup2(b.y), bb2 = dup2(b.z), bb3 = dup2(b.w);
            acc[0][0] = ffma2(am0, bb0, acc[0][0]); acc[0][1] = ffma2(am0, bb1, acc[0][1]);
            acc[0][2] = ffma2(am0, bb2, acc[0][2]); acc[0][3] = ffma2(am0, bb3, acc[0][3]);
            acc[1][0] = ffma2(am1, bb0, acc[1][0]); acc[1][1] = ffma2(am1, bb1, acc[1][1]);
            acc[1][2] = ffma2(am1, bb2, acc[1][2]); acc[1][3] = ffma2(am1, bb3, acc[1][3]);
            acc[2][0] = ffma2(am2, bb0, acc[2][0]); acc[2][1] = ffma2(am2, bb1, acc[2][1]);
            acc[2][2] = ffma2(am2, bb2, acc[2][2]); acc[2][3] = ffma2(am2, bb3, acc[2][3]);
            acc[3][0] = ffma2(am3, bb0, acc[3][0]); acc[3][1] = ffma2(am3, bb1, acc[3][1]);
            acc[3][2] = ffma2(am3, bb2, acc[3][2]); acc[3][3] = ffma2(am3, bb3, acc[3][3]);
        }
        __syncthreads();
    }

    float4 bv = make_float4(0.f, 0.f, 0.f, 0.f);
    if (bias) bv = *reinterpret_cast<const float4*>(bias + n0 + tx * 4);
#pragma unroll
    for (int i = 0; i < 4; i++) {
        float lo[4], hi[4];
#pragma unroll
        for (int j = 0; j < 4; j++) {
            lo[j] = __uint_as_float((unsigned)(acc[i][j] & 0xffffffffULL));
            hi[j] = __uint_as_float((unsigned)(acc[i][j] >> 32));
        }
        float4 ce = make_float4(lo[0] + bv.x, lo[1] + bv.y, lo[2] + bv.z, lo[3] + bv.w);
        float4 co = make_float4(hi[0] + bv.x, hi[1] + bv.y, hi[2] + bv.z, hi[3] + bv.w);
        if (RELU) {
            ce.x = fmaxf(ce.x, 0.f); ce.y = fmaxf(ce.y, 0.f);
            ce.z = fmaxf(ce.z, 0.f); ce.w = fmaxf(ce.w, 0.f);
            co.x = fmaxf(co.x, 0.f); co.y = fmaxf(co.y, 0.f);
            co.z = fmaxf(co.z, 0.f); co.w = fmaxf(co.w, 0.f);
        }
        int m = m0 + ty * 8 + i * 2;
        if (m < M)
            *reinterpret_cast<float4*>(C + (size_t)m * ldc + n0 + tx * 4) = ce;
        if (m + 1 < M)
            *reinterpret_cast<float4*>(C + (size_t)(m + 1) * ldc + n0 + tx * 4) = co;
    }
}

// ---------------- GAT attention logits ------------
__global__ void alpha4_kernel(const float* __restrict__ h, const float* __restrict__ av,
                              const float* __restrict__ dv, float* __restrict__ als,
                              float* __restrict__ ald)
{
    int idx = blockIdx.x * blockDim.x + threadIdx.x;
    if (idx >= NN * 4) return;
    int i = idx >> 2, hh = idx & 3;
    const float* hp = h + (size_t)i * 256 + hh * 64;
    const float* ap = av + hh * 64;
    const float* dp = dv + hh * 64;
    float ss = 0.f, sd = 0.f;
#pragma unroll
    for (int c = 0; c < 64; c++) { float v = hp[c]; ss += v * ap[c]; sd += v * dp[c]; }
    als[idx] = ss; ald[idx] = sd;
}

__global__ void alpha1_kernel(const float* __restrict__ h, const float* __restrict__ av,
                              const float* __restrict__ dv, float* __restrict__ als,
                              float* __restrict__ ald)
{
    int i = blockIdx.x * blockDim.x + threadIdx.x;
    if (i >= NN) return;
    const float* hp = h + (size_t)i * 64;
    float ss = 0.f, sd = 0.f;
#pragma unroll
    for (int c = 0; c < 64; c++) { float v = hp[c]; ss += v * av[c]; sd += v * dv[c]; }
    als[i] = ss; ald[i] = sd;
}

// ---------------- decoder stage 2 ------------
__global__ void decoder2_kernel(const float* __restrict__ d1, const float* __restrict__ Wd2,
                                const float* __restrict__ bd2, float* __restrict__ out)
{
    int e = blockIdx.x * blockDim.x + threadIdx.x;
    if (e >= EE) return;
    const float* r = d1 + (size_t)e * 64;
    float s = 0.f;
#pragma unroll
    for (int c = 0; c < 64; c++) s += r[c] * Wd2[c];
    out[e] = s + bd2[0];
}

// ---------------- host orchestration ------------
static inline dim3 ggrid(int M, int Ntot) { return dim3((M + 127) / 128, Ntot / 64); }
static inline int gb(int n) { return (n + 255) / 256; }

extern "C" void kernel_launch(void* const* d_in, const int* in_sizes, int n_in,
                              void* d_out, int out_size)
{
    (void)in_sizes; (void)n_in; (void)out_size;
    const float* x_seq  = (const float*)d_in[0];
    const int*   ei     = (const int*)d_in[1];
    const float* W1     = (const float*)d_in[2];
    const float* a_src1 = (const float*)d_in[3];
    const float* a_dst1 = (const float*)d_in[4];
    const float* b1     = (const float*)d_in[5];
    const float* W2     = (const float*)d_in[6];
    const float* a_src2 = (const float*)d_in[7];
    const float* a_dst2 = (const float*)d_in[8];
    const float* b2     = (const float*)d_in[9];
    const float* Wih0   = (const float*)d_in[10];
    const float* Whh0   = (const float*)d_in[11];
    const float* bih0   = (const float*)d_in[12];
    const float* bhh0   = (const float*)d_in[13];
    const float* Wih1   = (const float*)d_in[14];
    const float* Whh1   = (const float*)d_in[15];
    const float* bih1   = (const float*)d_in[16];
    const float* bhh1   = (const float*)d_in[17];
    const float* Wd1    = (const float*)d_in[18];
    const float* bd1    = (const float*)d_in[19];
    const float* Wd2    = (const float*)d_in[20];
    const float* bd2    = (const float*)d_in[21];
    float* out = (float*)d_out;

    float *p_h1lin, *p_als1, *p_ald1, *p_out1;
    float *p_h2lin, *p_als2, *p_ald2, *p_h2;
    float *p_P, *p_Q, *p_h0, *p_h1s, *p_dec1;
    int *p_cnt, *p_ptr, *p_woff, *p_csr;
    __nv_bfloat16* p_wimg;
    cudaGetSymbolAddress((void**)&p_h1lin, g_h1lin);
    cudaGetSymbolAddress((void**)&p_als1, g_als1);
    cudaGetSymbolAddress((void**)&p_ald1, g_ald1);
    cudaGetSymbolAddress((void**)&p_out1, g_out1);
    cudaGetSymbolAddress((void**)&p_h2lin, g_h2lin);
    cudaGetSymbolAddress((void**)&p_als2, g_als2);
    cudaGetSymbolAddress((void**)&p_ald2, g_ald2);
    cudaGetSymbolAddress((void**)&p_h2, g_h2);
    cudaGetSymbolAddress((void**)&p_P, g_P);
    cudaGetSymbolAddress((void**)&p_Q, g_Q);
    cudaGetSymbolAddress((void**)&p_h0, g_h0);
    cudaGetSymbolAddress((void**)&p_h1s, g_h1s);
    cudaGetSymbolAddress((void**)&p_dec1, g_dec1);
    cudaGetSymbolAddress((void**)&p_cnt, g_cnt);
    cudaGetSymbolAddress((void**)&p_ptr, g_ptr);
    cudaGetSymbolAddress((void**)&p_woff, g_woff);
    cudaGetSymbolAddress((void**)&p_csr, g_csr_src);
    cudaGetSymbolAddress((void**)&p_wimg, g_wimg);

    cudaFuncSetAttribute(gru0_fused_kernel, cudaFuncAttributeMaxDynamicSharedMemorySize, F0_SMEM);
    cudaFuncSetAttribute(gru1_fused_kernel, cudaFuncAttributeMaxDynamicSharedMemorySize, F1_SMEM);

    const __nv_bfloat16* whh0h = p_wimg + 0 * W_ELEMS;
    const __nv_bfloat16* whh0l = p_wimg + 1 * W_ELEMS;
    const __nv_bfloat16* wih1h = p_wimg + 2 * W_ELEMS;
    const __nv_bfloat16* wih1l = p_wimg + 3 * W_ELEMS;
    const __nv_bfloat16* whh1h = p_wimg + 4 * W_ELEMS;
    const __nv_bfloat16* whh1l = p_wimg + 5 * W_ELEMS;

    // reset recurrent state every call
    cudaMemsetAsync(p_h0, 0, (size_t)EE * 128 * sizeof(float), 0);
    cudaMemsetAsync(p_h1s, 0, (size_t)EE * 128 * sizeof(float), 0);

    // weight conversion to bf16 hi/lo images
    conv_w_kernel<<<gb(W_ELEMS), 256>>>(Whh0, (__nv_bfloat16*)whh0h, (__nv_bfloat16*)whh0l);
    conv_w_kernel<<<gb(W_ELEMS), 256>>>(Wih1, (__nv_bfloat16*)wih1h, (__nv_bfloat16*)wih1l);
    conv_w_kernel<<<gb(W_ELEMS), 256>>>(Whh1, (__nv_bfloat16*)whh1h, (__nv_bfloat16*)whh1l);

    // ---- build dst-grouped CSR once per call (graph static across timesteps) ----
    cudaMemsetAsync(p_cnt, 0, NN * sizeof(int), 0);
    csr_count_kernel<<<gb(EE), 256>>>(ei, p_cnt);
    csr_scan_kernel<<<1, 1024>>>(p_cnt, p_ptr, p_woff);
    csr_scatter_kernel<<<gb(EE), 256>>>(ei, p_woff, p_csr);

    const int agg_grid = (NN + 7) / 8;

    for (int t = 0; t < T_STEPS; ++t) {
        const float* x_t = x_seq + (size_t)t * NN * 32;

        // ---- GAT layer 1 (CSR gather, no atomics) ----
        sgemm_kernel<false, false><<<ggrid(NN, 256), 256>>>(x_t, W1, nullptr, p_h1lin,
                                                            NN, 32, 256, 256);
        alpha4_kernel<<<gb(NN * 4), 256>>>(p_h1lin, a_src1, a_dst1, p_als1, p_ald1);
        gat1_agg_kernel<<<agg_grid, 256>>>(p_ptr, p_csr, p_h1lin, p_als1, p_ald1, b1, p_out1);

        // ---- GAT layer 2 ----
        sgemm_kernel<false, false><<<ggrid(NN, 64), 256>>>(p_out1, W2, nullptr, p_h2lin,
                                                           NN, 256, 64, 64);
        alpha1_kernel<<<gb(NN), 256>>>(p_h2lin, a_src2, a_dst2, p_als2, p_ald2);
        gat2_agg_kernel<<<agg_grid, 256>>>(p_ptr, p_csr, p_h2lin, p_als2, p_ald2, b2, p_h2);

        // ---- GRU layer 0: node-level P/Q, then fused GEMM+gate ----
        sgemm_kernel<true, false><<<ggrid(NN, 384), 256>>>(p_h2, Wih0, bih0, p_P,
                                                           NN, 64, 128, 384);
        sgemm_kernel<true, false><<<ggrid(NN, 384), 256>>>(p_h2, Wih0 + 64, nullptr, p_Q,
                                                           NN, 64, 128, 384);
        gru0_fused_kernel<<<EE / 64, 256, F0_SMEM>>>(ei, p_P, p_Q, p_h0,
            (const uint4*)whh0h, (const uint4*)whh0l, bhh0);

        // ---- GRU layer 1: fully fused ----
        gru1_fused_kernel<<<EE / 64, 256, F1_SMEM>>>(p_h0, p_h1s,
            (const uint4*)wih1h, (const uint4*)wih1l,
            (const uint4*)whh1h, (const uint4*)whh1l, bih1, bhh1);
    }

    // ---- decoder ----
    sgemm_kernel<false, true><<<ggrid(EE, 64), 256>>>(p_h1s, Wd1, bd1, p_dec1,
                                                      EE, 128, 64, 64);
    decoder2_kernel<<<gb(EE), 256>>>(p_dec1, Wd2, bd2, out);
}